// round 9
// baseline (speedup 1.0000x reference)
#include <cuda_runtime.h>
#include <math.h>
#include <stdint.h>

// ---------------- problem constants ----------------
#define CC 384
#define WS 7
#define NT 49
#define HEADS 12
#define HD 32
#define NWIN 1024
#define MROWS (NWIN * NT)   // 50176
#define C4 (CC / 4)

#if defined(__CUDA_ARCH_FEAT_SM103_ALL) || defined(__CUDA_ARCH_FEAT_SM100_ALL) || defined(__CUDA_ARCH_FEAT_SM101_ALL)
#define TC_OK 1
#else
#define TC_OK 0
#endif

// ---------------- scratch (device globals) ----------------
__device__ float g_xw[MROWS * CC];
__device__ float g_h[MROWS * CC];
__device__ float g_qkv[MROWS * 3 * CC];
__device__ float g_o[MROWS * CC];
__device__ float g_hidden[MROWS * 4 * CC];
#define WT_LAYER 1769472
__device__ float g_wT[2 * WT_LAYER];

#define OFF_QKV  0
#define OFF_PROJ 442368
#define OFF_W1   589824
#define OFF_W2   1179648

// ---------------- small helpers ----------------
__device__ __forceinline__ float to_tf32(float x) {
    uint32_t u;
    asm("cvt.rna.tf32.f32 %0, %1;" : "=r"(u) : "f"(x));
    return __uint_as_float(u);
}
__device__ __forceinline__ uint32_t smem_u32(const void* p) {
    uint32_t a;
    asm("{ .reg .u64 t; cvta.to.shared.u64 t, %1; cvt.u32.u64 %0, t; }" : "=r"(a) : "l"(p));
    return a;
}
__device__ __forceinline__ void cp16(uint32_t dst, const void* src) {
    asm volatile("cp.async.cg.shared.global [%0], [%1], 16;" :: "r"(dst), "l"(src));
}

// SW64 swizzle (64B rows): bits[5:4] ^= bits[8:7]
#define SWZ64(o) ((o) ^ (((o) >> 3) & 0x30))
// SW64 K-major smem descriptor: layout=4, version=1, SBO=32 (512B atom), LBO=1
#define DESC_SW64 ((4ull << 61) | (1ull << 46) | (32ull << 32) | (1ull << 16))
// idesc tf32: dtype=f32(1<<4), atype/btype=tf32, N=192 (24<<17), M=128 (8<<24)
#define IDESC_TF32_N192 0x08300910u

#define STAGE_BYTES 20480           // A 8KB + B 12KB
#define NSTAGE 4
#define NTILE 192

#if TC_OK
__device__ __forceinline__ void mbar_wait(uint32_t mb, int parity) {
    asm volatile(
        "{\n\t.reg .pred P;\n"
        "W%=:\n\t"
        "mbarrier.try_wait.parity.acquire.cta.shared::cta.b64 P, [%0], %1, 0x989680;\n\t"
        "@P bra D%=;\n\t"
        "bra W%=;\n"
        "D%=:\n\t}"
        :: "r"(mb), "r"(parity) : "memory");
}
__device__ __forceinline__ void mma_tf32_ss(uint32_t d, uint64_t a, uint64_t b,
                                            uint32_t idesc, uint32_t en) {
    asm volatile(
        "{\n\t.reg .pred p;\n\t"
        "setp.ne.u32 p, %4, 0;\n\t"
        "tcgen05.mma.cta_group::1.kind::tf32 [%0], %1, %2, %3, p;\n\t}"
        :: "r"(d), "l"(a), "l"(b), "r"(idesc), "r"(en) : "memory");
}
#define LDTM_X32(r, a) \
    asm volatile("tcgen05.ld.sync.aligned.32x32b.x32.b32 " \
        "{%0,%1,%2,%3,%4,%5,%6,%7,%8,%9,%10,%11,%12,%13,%14,%15," \
        "%16,%17,%18,%19,%20,%21,%22,%23,%24,%25,%26,%27,%28,%29,%30,%31}, [%32];" \
        : "=r"((r)[0]),"=r"((r)[1]),"=r"((r)[2]),"=r"((r)[3]),"=r"((r)[4]),"=r"((r)[5]),"=r"((r)[6]),"=r"((r)[7]), \
          "=r"((r)[8]),"=r"((r)[9]),"=r"((r)[10]),"=r"((r)[11]),"=r"((r)[12]),"=r"((r)[13]),"=r"((r)[14]),"=r"((r)[15]), \
          "=r"((r)[16]),"=r"((r)[17]),"=r"((r)[18]),"=r"((r)[19]),"=r"((r)[20]),"=r"((r)[21]),"=r"((r)[22]),"=r"((r)[23]), \
          "=r"((r)[24]),"=r"((r)[25]),"=r"((r)[26]),"=r"((r)[27]),"=r"((r)[28]),"=r"((r)[29]),"=r"((r)[30]),"=r"((r)[31]) \
        : "r"(a))
#endif

// ---------------- window partition / un-partition ----------------
__global__ void win_partition(const float4* __restrict__ x, float4* __restrict__ xw) {
    int t = blockIdx.x * blockDim.x + threadIdx.x;
    if (t >= MROWS * C4) return;
    int r = t / C4, c4 = t - r * C4;
    int w = r / NT, tt = r - w * NT;
    int b = w >> 6, wrem = w & 63, wy = wrem >> 3, wx = wrem & 7;
    int ty = tt / WS, tx = tt - ty * WS;
    int src = ((b * 56 + wy * WS + ty) * 56 + wx * WS + tx) * C4 + c4;
    xw[t] = x[src];
}
__global__ void win_unpartition(const float4* __restrict__ xw, float4* __restrict__ out) {
    int t = blockIdx.x * blockDim.x + threadIdx.x;
    if (t >= MROWS * C4) return;
    int r = t / C4, c4 = t - r * C4;
    int w = r / NT, tt = r - w * NT;
    int b = w >> 6, wrem = w & 63, wy = wrem >> 3, wx = wrem & 7;
    int ty = tt / WS, tx = tt - ty * WS;
    int dst = ((b * 56 + wy * WS + ty) * 56 + wx * WS + tx) * C4 + c4;
    out[dst] = xw[t];
}

// ---------------- fused weight transpose (all 4 weights, both layers) ----------------
__global__ void transpose_all(const float* __restrict__ qkv_w,
                              const float* __restrict__ proj_w,
                              const float* __restrict__ w1,
                              const float* __restrict__ w2,
                              float* __restrict__ wT) {
    __shared__ float t[32][33];
    int id = blockIdx.x, l = blockIdx.y;
    const float* src; size_t doff; int K, N, tn;
    if (id < 432)       { src = qkv_w  + (size_t)l*384*1152; doff = OFF_QKV;  K = 384;  N = 1152; tn = 36; }
    else if (id < 576)  { id -= 432; src = proj_w + (size_t)l*384*384;  doff = OFF_PROJ; K = 384;  N = 384;  tn = 12; }
    else if (id < 1152) { id -= 576; src = w1     + (size_t)l*384*1536; doff = OFF_W1;   K = 384;  N = 1536; tn = 48; }
    else                { id -= 1152; src = w2    + (size_t)l*1536*384; doff = OFF_W2;   K = 1536; N = 384;  tn = 12; }
    float* dst = wT + (size_t)l * WT_LAYER + doff;
    int k0 = (id / tn) * 32, n0 = (id % tn) * 32;
    int tx = threadIdx.x, ty = threadIdx.y;
    #pragma unroll
    for (int i = 0; i < 32; i += 8)
        t[ty + i][tx] = src[(size_t)(k0 + ty + i) * N + n0 + tx];
    __syncthreads();
    #pragma unroll
    for (int i = 0; i < 32; i += 8)
        dst[(size_t)(n0 + ty + i) * K + k0 + tx] = to_tf32(t[tx][ty + i]);
}

// ---------------- layernorm (rounds output to tf32) ----------------
__global__ __launch_bounds__(256) void ln_kernel(const float* __restrict__ xin,
                                                 const float* __restrict__ sc,
                                                 const float* __restrict__ bi,
                                                 float* __restrict__ outp) {
    int warp = threadIdx.x >> 5, lane = threadIdx.x & 31;
    int row = blockIdx.x * 8 + warp;
    const float4* xr = (const float4*)(xin + (size_t)row * CC);
    float4 v0 = xr[lane], v1 = xr[lane + 32], v2 = xr[lane + 64];
    float s = v0.x + v0.y + v0.z + v0.w + v1.x + v1.y + v1.z + v1.w + v2.x + v2.y + v2.z + v2.w;
    float s2 = v0.x*v0.x + v0.y*v0.y + v0.z*v0.z + v0.w*v0.w
             + v1.x*v1.x + v1.y*v1.y + v1.z*v1.z + v1.w*v1.w
             + v2.x*v2.x + v2.y*v2.y + v2.z*v2.z + v2.w*v2.w;
    #pragma unroll
    for (int o = 16; o; o >>= 1) {
        s  += __shfl_xor_sync(0xffffffffu, s, o);
        s2 += __shfl_xor_sync(0xffffffffu, s2, o);
    }
    float mu = s * (1.0f / CC);
    float var = s2 * (1.0f / CC) - mu * mu;
    float rstd = rsqrtf(var + 1e-6f);
    const float4* s4 = (const float4*)sc;
    const float4* b4 = (const float4*)bi;
    float4* orow = (float4*)(outp + (size_t)row * CC);
    #pragma unroll
    for (int c = 0; c < 3; c++) {
        float4 v = c == 0 ? v0 : (c == 1 ? v1 : v2);
        float4 g = s4[lane + c * 32], bb = b4[lane + c * 32], r;
        r.x = to_tf32((v.x - mu) * rstd * g.x + bb.x);
        r.y = to_tf32((v.y - mu) * rstd * g.y + bb.y);
        r.z = to_tf32((v.z - mu) * rstd * g.z + bb.z);
        r.w = to_tf32((v.w - mu) * rstd * g.w + bb.w);
        orow[lane + c * 32] = r;
    }
}

// ---------------- gelu ----------------
__device__ __forceinline__ float gelu_tanh(float x) {
    float x3 = x * x * x;
    return 0.5f * x * (1.0f + tanhf(0.7978845608028654f * (x + 0.044715f * x3)));
}

// ---------------- GEMM: C[M,N] = A[M,K] * B[N,K]^T ; CTA tile 128x192 ----------------
// TMEM alloc 256 cols -> two CTAs per SM hold TMEM concurrently (512 total).
// K-stage = 16 (SW64): stage = A 8KB + B 12KB = 20KB; 4-stage ring = 80KB.
// 288 threads: warps 0-7 load, warp 8 lane 0 issues MMAs.
// EPI: 0 none | 2 gelu(acc+bias)+tf32round | 3 acc+bias+res | 4 acc+res
template <int EPI>
__global__ __launch_bounds__(288) void tc_gemm(const float* __restrict__ A,
                                               const float* __restrict__ B,
                                               const float* __restrict__ bias,
                                               const float* __restrict__ res,
                                               float* __restrict__ C,
                                               int K, int N) {
    extern __shared__ char smem[];
#if TC_OK
    uint32_t raw = smem_u32(smem);
    uint32_t base = (raw + 1023) & ~1023u;
    uint32_t ctrl = base + NSTAGE * STAGE_BYTES;
    uint32_t fullb[NSTAGE], doneb[NSTAGE];
    #pragma unroll
    for (int i = 0; i < NSTAGE; i++) { fullb[i] = ctrl + i * 8; doneb[i] = ctrl + 32 + i * 8; }
    uint32_t tptr = ctrl + 64;
    int tid = threadIdx.x, wid = tid >> 5, lane = tid & 31;
    int m0 = blockIdx.x << 7;
    int n0 = blockIdx.y * NTILE;
    int S = K >> 4;   // K stages of 16 (24 or 96)

    auto load_stage = [&](int s) {   // tid < 256 only
        int b = s & (NSTAGE - 1);
        uint32_t st = base + b * STAGE_BYTES;
        int k0 = s << 4;
        #pragma unroll
        for (int i = 0; i < 5; i++) {
            int g = (i << 8) + tid;            // 0..1279 16B-chunks
            uint32_t dst;
            const float* src;
            if (g < 512) {                     // A tile: 128 rows x 64B
                int row = g >> 2, cb = (g & 3) << 4;
                dst = st + SWZ64(row * 64 + cb);
                src = A + (size_t)(m0 + row) * K + k0 + (cb >> 2);
            } else {                           // B tile: 192 rows x 64B
                int w = g - 512;
                int row = w >> 2, cb = (w & 3) << 4;
                dst = st + 8192 + SWZ64(row * 64 + cb);
                src = B + (size_t)(n0 + row) * K + k0 + (cb >> 2);
            }
            cp16(dst, src);
        }
        asm volatile("cp.async.mbarrier.arrive.noinc.shared::cta.b64 [%0];"
                     :: "r"(fullb[b]) : "memory");
    };

    if (wid == 0) {
        asm volatile("tcgen05.alloc.cta_group::1.sync.aligned.shared::cta.b32 [%0], %1;"
                     :: "r"(tptr), "r"(256) : "memory");
        asm volatile("tcgen05.relinquish_alloc_permit.cta_group::1.sync.aligned;");
    }
    if (tid == 0) {
        #pragma unroll
        for (int i = 0; i < NSTAGE; i++) {
            asm volatile("mbarrier.init.shared.b64 [%0], 256;" :: "r"(fullb[i]) : "memory");
            asm volatile("mbarrier.init.shared.b64 [%0], 1;"   :: "r"(doneb[i]) : "memory");
        }
    }
    __syncthreads();
    uint32_t tmem;
    asm volatile("ld.shared.b32 %0, [%1];" : "=r"(tmem) : "r"(tptr));

    if (tid < 256) {
        load_stage(0);
        load_stage(1);
        load_stage(2);
        load_stage(3);
    }

    if (wid == 8) {
        if (lane == 0) {
            int fph[NSTAGE] = {0, 0, 0, 0};
            for (int s = 0; s < S; s++) {
                int b = s & (NSTAGE - 1);
                mbar_wait(fullb[b], fph[b]); fph[b] ^= 1;
                asm volatile("fence.proxy.async.shared::cta;" ::: "memory");
                uint32_t st = base + b * STAGE_BYTES;
                uint64_t ad = DESC_SW64 | ((uint64_t)(st >> 4) & 0x3FFF);
                uint64_t bd = DESC_SW64 | ((uint64_t)((st + 8192) >> 4) & 0x3FFF);
                #pragma unroll
                for (int ks = 0; ks < 2; ks++)
                    mma_tf32_ss(tmem, ad + 2 * ks, bd + 2 * ks,
                                IDESC_TF32_N192, (s | ks) != 0);
                asm volatile("tcgen05.commit.cta_group::1.mbarrier::arrive::one.shared::cluster.b64 [%0];"
                             :: "r"(doneb[b]) : "memory");
            }
        }
    } else {
        int dph[NSTAGE] = {0, 0, 0, 0};
        for (int s = NSTAGE; s < S; s++) {
            int b = s & (NSTAGE - 1);
            mbar_wait(doneb[b], dph[b]); dph[b] ^= 1;
            load_stage(s);
        }
        int bl = (S - 1) & (NSTAGE - 1);
        mbar_wait(doneb[bl], dph[bl]);
    }
    __syncthreads();

    asm volatile("tcgen05.fence::after_thread_sync;" ::: "memory");
    if (wid < 8) {
        int row = m0 + ((wid & 3) << 5) + lane;
        int colHalf = (wid >> 2) * 96;           // 0 or 96
        uint32_t toff = tmem + ((uint32_t)(wid & 3) << 21);
        #pragma unroll
        for (int g = 0; g < 3; g++) {
            int col = colHalf + g * 32;
            uint32_t r[32];
            LDTM_X32(r, toff + col);
            asm volatile("tcgen05.wait::ld.sync.aligned;" ::: "memory");
            float* crow = C + (size_t)row * N + n0 + col;
            const float4* rrow = (EPI == 3 || EPI == 4)
                ? (const float4*)(res + (size_t)row * N + n0 + col) : nullptr;
            const float4* b4 = (EPI == 2 || EPI == 3)
                ? (const float4*)(bias + n0 + col) : nullptr;
            #pragma unroll
            for (int j = 0; j < 32; j += 4) {
                float4 v;
                v.x = __uint_as_float(r[j + 0]);
                v.y = __uint_as_float(r[j + 1]);
                v.z = __uint_as_float(r[j + 2]);
                v.w = __uint_as_float(r[j + 3]);
                if (EPI == 2 || EPI == 3) {
                    float4 bb = b4[j >> 2];
                    v.x += bb.x; v.y += bb.y; v.z += bb.z; v.w += bb.w;
                }
                if (EPI == 2) {
                    v.x = to_tf32(gelu_tanh(v.x)); v.y = to_tf32(gelu_tanh(v.y));
                    v.z = to_tf32(gelu_tanh(v.z)); v.w = to_tf32(gelu_tanh(v.w));
                }
                if (EPI == 3 || EPI == 4) {
                    float4 rr = rrow[j >> 2];
                    v.x += rr.x; v.y += rr.y; v.z += rr.z; v.w += rr.w;
                }
                *(float4*)(crow + j) = v;
            }
        }
    }
    __syncthreads();
    if (wid == 0)
        asm volatile("tcgen05.dealloc.cta_group::1.sync.aligned.b32 %0, %1;"
                     :: "r"(tmem), "r"(256));
#else
    // ---------- SIMT fallback (plain sm_103 target; never selected at runtime) ----------
    (void)smem;
    int tid = threadIdx.x;
    int m0 = blockIdx.x << 7;
    int n0 = blockIdx.y * NTILE;
    for (int e = tid; e < 128 * NTILE; e += 288) {
        int i = e / NTILE, j = e % NTILE;
        int row = m0 + i, coln = n0 + j;
        float acc = 0.0f;
        for (int k = 0; k < K; k++)
            acc += A[(size_t)row * K + k] * B[(size_t)coln * K + k];
        float v = acc;
        if (EPI == 2 || EPI == 3) v += bias[coln];
        if (EPI == 2) v = to_tf32(gelu_tanh(v));
        if (EPI == 3 || EPI == 4) v += res[(size_t)row * N + coln];
        C[(size_t)row * N + coln] = v;
    }
#endif
}

// ---------------- windowed attention: register-tiled, float4 ----------------
__global__ __launch_bounds__(224) void attn_kernel(const float* __restrict__ qkv,
                                                   const float* __restrict__ rpb,
                                                   float* __restrict__ o) {
    __shared__ float sQ[NT * 32];
    __shared__ float sK[NT * 36];
    __shared__ float sV[NT * 32];
    __shared__ float sS[NT * 52];
    __shared__ float sB[169];

    int w = blockIdx.x / HEADS, hh = blockIdx.x % HEADS;
    int tid = threadIdx.x, warp = tid >> 5, lane = tid & 31;
    const float* basep = qkv + (size_t)(w * NT) * (3 * CC) + hh * HD;

    for (int i = tid; i < NT * 8; i += 224) {
        int t = i >> 3, d4 = i & 7;
        const float4* p = (const float4*)(basep + (size_t)t * (3 * CC));
        *(float4*)&sQ[t * 32 + d4 * 4] = p[d4];
        *(float4*)&sK[t * 36 + d4 * 4] = p[96 + d4];
        *(float4*)&sV[t * 32 + d4 * 4] = p[192 + d4];
    }
    for (int i = tid; i < 169; i += 224) sB[i] = rpb[i * HEADS + hh];
    __syncthreads();

    const float scale = 0.17677669529663687f;
    int q0 = warp * 7;
    int k1 = lane, k2 = lane + 32;

    {
        float a0[7], a1[7];
        #pragma unroll
        for (int i = 0; i < 7; i++) { a0[i] = 0.0f; a1[i] = 0.0f; }
        #pragma unroll
        for (int d4 = 0; d4 < 8; d4++) {
            float4 kv1 = *(const float4*)&sK[k1 * 36 + d4 * 4];
            float4 kv2 = (k2 < NT) ? *(const float4*)&sK[k2 * 36 + d4 * 4]
                                   : make_float4(0.f, 0.f, 0.f, 0.f);
            #pragma unroll
            for (int i = 0; i < 7; i++) {
                float4 qv = *(const float4*)&sQ[(q0 + i) * 32 + d4 * 4];
                a0[i] += qv.x * kv1.x + qv.y * kv1.y + qv.z * kv1.z + qv.w * kv1.w;
                a1[i] += qv.x * kv2.x + qv.y * kv2.y + qv.z * kv2.z + qv.w * kv2.w;
            }
        }
        int k1y = k1 / WS, k1x = k1 - k1y * WS;
        int k2y = k2 / WS, k2x = k2 - k2y * WS;
        #pragma unroll
        for (int i = 0; i < 7; i++) {
            int q = q0 + i;
            int qy = q / WS, qx = q - qy * WS;
            sS[q * 52 + k1] = a0[i] * scale + sB[(qy - k1y + 6) * 13 + (qx - k1x + 6)];
            if (k2 < NT)
                sS[q * 52 + k2] = a1[i] * scale + sB[(qy - k2y + 6) * 13 + (qx - k2x + 6)];
        }
    }
    __syncthreads();

    #pragma unroll
    for (int i = 0; i < 7; i++) {
        int row = q0 + i;
        float v0 = sS[row * 52 + lane];
        float v1 = (lane < 17) ? sS[row * 52 + 32 + lane] : -INFINITY;
        float m = fmaxf(v0, v1);
        #pragma unroll
        for (int ofs = 16; ofs; ofs >>= 1) m = fmaxf(m, __shfl_xor_sync(0xffffffffu, m, ofs));
        float e0 = expf(v0 - m);
        float e1 = (lane < 17) ? expf(v1 - m) : 0.0f;
        float sum = e0 + e1;
        #pragma unroll
        for (int ofs = 16; ofs; ofs >>= 1) sum += __shfl_xor_sync(0xffffffffu, sum, ofs);
        float inv = 1.0f / sum;
        sS[row * 52 + lane] = e0 * inv;
        if (lane < 17) sS[row * 52 + 32 + lane] = e1 * inv;
    }
    __syncthreads();

    {
        float outv[7];
        #pragma unroll
        for (int i = 0; i < 7; i++) outv[i] = 0.0f;
        #pragma unroll
        for (int k4 = 0; k4 < 48; k4 += 4) {
            float vk0 = sV[(k4 + 0) * 32 + lane];
            float vk1 = sV[(k4 + 1) * 32 + lane];
            float vk2 = sV[(k4 + 2) * 32 + lane];
            float vk3 = sV[(k4 + 3) * 32 + lane];
            #pragma unroll
            for (int i = 0; i < 7; i++) {
                float4 sv = *(const float4*)&sS[(q0 + i) * 52 + k4];
                outv[i] += sv.x * vk0 + sv.y * vk1 + sv.z * vk2 + sv.w * vk3;
            }
        }
        float vkl = sV[48 * 32 + lane];
        #pragma unroll
        for (int i = 0; i < 7; i++) outv[i] += sS[(q0 + i) * 52 + 48] * vkl;
        #pragma unroll
        for (int i = 0; i < 7; i++)
            o[(size_t)(w * NT + q0 + i) * CC + hh * HD + lane] = to_tf32(outv[i]);
    }
}

// ---------------- launch ----------------
extern "C" void kernel_launch(void* const* d_in, const int* in_sizes, int n_in,
                              void* d_out, int out_size) {
    const float* x      = (const float*)d_in[0];
    const float* ln1_s  = (const float*)d_in[1];
    const float* ln1_b  = (const float*)d_in[2];
    const float* qkv_w  = (const float*)d_in[3];
    const float* rpb    = (const float*)d_in[4];
    const float* proj_w = (const float*)d_in[5];
    const float* ln2_s  = (const float*)d_in[6];
    const float* ln2_b  = (const float*)d_in[7];
    const float* mlp_w1 = (const float*)d_in[8];
    const float* mlp_b1 = (const float*)d_in[9];
    const float* mlp_w2 = (const float*)d_in[10];
    const float* mlp_b2 = (const float*)d_in[11];
    float* out = (float*)d_out;

    float *xw, *h, *qkv, *o, *hidden, *wT;
    cudaGetSymbolAddress((void**)&xw, g_xw);
    cudaGetSymbolAddress((void**)&h, g_h);
    cudaGetSymbolAddress((void**)&qkv, g_qkv);
    cudaGetSymbolAddress((void**)&o, g_o);
    cudaGetSymbolAddress((void**)&hidden, g_hidden);
    cudaGetSymbolAddress((void**)&wT, g_wT);

    const int SMEM_SZ = 1024 + NSTAGE * STAGE_BYTES + 128;
    cudaFuncSetAttribute(tc_gemm<0>, cudaFuncAttributeMaxDynamicSharedMemorySize, SMEM_SZ);
    cudaFuncSetAttribute(tc_gemm<2>, cudaFuncAttributeMaxDynamicSharedMemorySize, SMEM_SZ);
    cudaFuncSetAttribute(tc_gemm<3>, cudaFuncAttributeMaxDynamicSharedMemorySize, SMEM_SZ);
    cudaFuncSetAttribute(tc_gemm<4>, cudaFuncAttributeMaxDynamicSharedMemorySize, SMEM_SZ);

    transpose_all<<<dim3(1728, 2), dim3(32, 8)>>>(qkv_w, proj_w, mlp_w1, mlp_w2, wT);

    int nElem4 = MROWS * C4;
    win_partition<<<(nElem4 + 255) / 256, 256>>>((const float4*)x, (float4*)xw);

    const int MT = MROWS / 128;  // 392
    for (int l = 0; l < 2; l++) {
        float* wl = wT + (size_t)l * WT_LAYER;
        ln_kernel<<<MROWS / 8, 256>>>(xw, ln1_s + l * CC, ln1_b + l * CC, h);
        tc_gemm<0><<<dim3(MT, 6), 288, SMEM_SZ>>>(h, wl + OFF_QKV, nullptr, nullptr, qkv, 384, 1152);
        attn_kernel<<<NWIN * HEADS, 224>>>(qkv, rpb + (size_t)l * 169 * HEADS, o);
        tc_gemm<4><<<dim3(MT, 2), 288, SMEM_SZ>>>(o, wl + OFF_PROJ, nullptr, xw, xw, 384, 384);
        ln_kernel<<<MROWS / 8, 256>>>(xw, ln2_s + l * CC, ln2_b + l * CC, h);
        tc_gemm<2><<<dim3(MT, 8), 288, SMEM_SZ>>>(h, wl + OFF_W1, mlp_b1 + (size_t)l * 1536,
                                                   nullptr, hidden, 384, 1536);
        tc_gemm<3><<<dim3(MT, 2), 288, SMEM_SZ>>>(hidden, wl + OFF_W2, mlp_b2 + (size_t)l * 384,
                                                  xw, xw, 1536, 384);
    }

    win_unpartition<<<(nElem4 + 255) / 256, 256>>>((const float4*)xw, (float4*)out);
}

// round 10
// speedup vs baseline: 1.0945x; 1.0945x over previous
#include <cuda_runtime.h>
#include <math.h>
#include <stdint.h>

// ---------------- problem constants ----------------
#define CC 384
#define WS 7
#define NT 49
#define HEADS 12
#define HD 32
#define NWIN 1024
#define MROWS (NWIN * NT)   // 50176
#define C4 (CC / 4)

#if defined(__CUDA_ARCH_FEAT_SM103_ALL) || defined(__CUDA_ARCH_FEAT_SM100_ALL) || defined(__CUDA_ARCH_FEAT_SM101_ALL)
#define TC_OK 1
#else
#define TC_OK 0
#endif

// ---------------- scratch (device globals) ----------------
__device__ float g_xw[MROWS * CC];
__device__ float g_h[MROWS * CC];
__device__ float g_qkv[MROWS * 3 * CC];
__device__ float g_o[MROWS * CC];
__device__ float g_hidden[MROWS * 4 * CC];
#define WT_LAYER 1769472
__device__ float g_wT[2 * WT_LAYER];

#define OFF_QKV  0
#define OFF_PROJ 442368
#define OFF_W1   589824
#define OFF_W2   1179648

// ---------------- small helpers ----------------
__device__ __forceinline__ float to_tf32(float x) {
    uint32_t u;
    asm("cvt.rna.tf32.f32 %0, %1;" : "=r"(u) : "f"(x));
    return __uint_as_float(u);
}
__device__ __forceinline__ uint32_t smem_u32(const void* p) {
    uint32_t a;
    asm("{ .reg .u64 t; cvta.to.shared.u64 t, %1; cvt.u32.u64 %0, t; }" : "=r"(a) : "l"(p));
    return a;
}
__device__ __forceinline__ void cp16(uint32_t dst, const void* src) {
    asm volatile("cp.async.cg.shared.global [%0], [%1], 16;" :: "r"(dst), "l"(src));
}

// SW64 swizzle (64B rows): bits[5:4] ^= bits[8:7]
#define SWZ64(o) ((o) ^ (((o) >> 3) & 0x30))
// SW64 K-major smem descriptor: layout=4, version=1, SBO=32 (512B atom), LBO=1
#define DESC_SW64 ((4ull << 61) | (1ull << 46) | (32ull << 32) | (1ull << 16))
#define IDESC_TF32 0x08200910u

#if TC_OK
__device__ __forceinline__ void mbar_wait(uint32_t mb, int parity) {
    asm volatile(
        "{\n\t.reg .pred P;\n"
        "W%=:\n\t"
        "mbarrier.try_wait.parity.acquire.cta.shared::cta.b64 P, [%0], %1, 0x989680;\n\t"
        "@P bra D%=;\n\t"
        "bra W%=;\n"
        "D%=:\n\t}"
        :: "r"(mb), "r"(parity) : "memory");
}
__device__ __forceinline__ void mbar_arrive(uint32_t mb) {
    asm volatile("mbarrier.arrive.shared.b64 _, [%0];" :: "r"(mb) : "memory");
}
__device__ __forceinline__ void mma_tf32_ss(uint32_t d, uint64_t a, uint64_t b,
                                            uint32_t idesc, uint32_t en) {
    asm volatile(
        "{\n\t.reg .pred p;\n\t"
        "setp.ne.u32 p, %4, 0;\n\t"
        "tcgen05.mma.cta_group::1.kind::tf32 [%0], %1, %2, %3, p;\n\t}"
        :: "r"(d), "l"(a), "l"(b), "r"(idesc), "r"(en) : "memory");
}
#define LDTM_X32(r, a) \
    asm volatile("tcgen05.ld.sync.aligned.32x32b.x32.b32 " \
        "{%0,%1,%2,%3,%4,%5,%6,%7,%8,%9,%10,%11,%12,%13,%14,%15," \
        "%16,%17,%18,%19,%20,%21,%22,%23,%24,%25,%26,%27,%28,%29,%30,%31}, [%32];" \
        : "=r"((r)[0]),"=r"((r)[1]),"=r"((r)[2]),"=r"((r)[3]),"=r"((r)[4]),"=r"((r)[5]),"=r"((r)[6]),"=r"((r)[7]), \
          "=r"((r)[8]),"=r"((r)[9]),"=r"((r)[10]),"=r"((r)[11]),"=r"((r)[12]),"=r"((r)[13]),"=r"((r)[14]),"=r"((r)[15]), \
          "=r"((r)[16]),"=r"((r)[17]),"=r"((r)[18]),"=r"((r)[19]),"=r"((r)[20]),"=r"((r)[21]),"=r"((r)[22]),"=r"((r)[23]), \
          "=r"((r)[24]),"=r"((r)[25]),"=r"((r)[26]),"=r"((r)[27]),"=r"((r)[28]),"=r"((r)[29]),"=r"((r)[30]),"=r"((r)[31]) \
        : "r"(a))
#endif

// ---------------- window partition / un-partition ----------------
__global__ void win_partition(const float4* __restrict__ x, float4* __restrict__ xw) {
    int t = blockIdx.x * blockDim.x + threadIdx.x;
    if (t >= MROWS * C4) return;
    int r = t / C4, c4 = t - r * C4;
    int w = r / NT, tt = r - w * NT;
    int b = w >> 6, wrem = w & 63, wy = wrem >> 3, wx = wrem & 7;
    int ty = tt / WS, tx = tt - ty * WS;
    int src = ((b * 56 + wy * WS + ty) * 56 + wx * WS + tx) * C4 + c4;
    xw[t] = x[src];
}
__global__ void win_unpartition(const float4* __restrict__ xw, float4* __restrict__ out) {
    int t = blockIdx.x * blockDim.x + threadIdx.x;
    if (t >= MROWS * C4) return;
    int r = t / C4, c4 = t - r * C4;
    int w = r / NT, tt = r - w * NT;
    int b = w >> 6, wrem = w & 63, wy = wrem >> 3, wx = wrem & 7;
    int ty = tt / WS, tx = tt - ty * WS;
    int dst = ((b * 56 + wy * WS + ty) * 56 + wx * WS + tx) * C4 + c4;
    out[dst] = xw[t];
}

// ---------------- fused weight transpose (all 4 weights, both layers) ----------------
__global__ void transpose_all(const float* __restrict__ qkv_w,
                              const float* __restrict__ proj_w,
                              const float* __restrict__ w1,
                              const float* __restrict__ w2,
                              float* __restrict__ wT) {
    __shared__ float t[32][33];
    int id = blockIdx.x, l = blockIdx.y;
    const float* src; size_t doff; int K, N, tn;
    if (id < 432)       { src = qkv_w  + (size_t)l*384*1152; doff = OFF_QKV;  K = 384;  N = 1152; tn = 36; }
    else if (id < 576)  { id -= 432; src = proj_w + (size_t)l*384*384;  doff = OFF_PROJ; K = 384;  N = 384;  tn = 12; }
    else if (id < 1152) { id -= 576; src = w1     + (size_t)l*384*1536; doff = OFF_W1;   K = 384;  N = 1536; tn = 48; }
    else                { id -= 1152; src = w2    + (size_t)l*1536*384; doff = OFF_W2;   K = 1536; N = 384;  tn = 12; }
    float* dst = wT + (size_t)l * WT_LAYER + doff;
    int k0 = (id / tn) * 32, n0 = (id % tn) * 32;
    int tx = threadIdx.x, ty = threadIdx.y;
    #pragma unroll
    for (int i = 0; i < 32; i += 8)
        t[ty + i][tx] = src[(size_t)(k0 + ty + i) * N + n0 + tx];
    __syncthreads();
    #pragma unroll
    for (int i = 0; i < 32; i += 8)
        dst[(size_t)(n0 + ty + i) * K + k0 + tx] = to_tf32(t[tx][ty + i]);
}

// ---------------- layernorm (rounds output to tf32) ----------------
__global__ __launch_bounds__(256) void ln_kernel(const float* __restrict__ xin,
                                                 const float* __restrict__ sc,
                                                 const float* __restrict__ bi,
                                                 float* __restrict__ outp) {
    int warp = threadIdx.x >> 5, lane = threadIdx.x & 31;
    int row = blockIdx.x * 8 + warp;
    const float4* xr = (const float4*)(xin + (size_t)row * CC);
    float4 v0 = xr[lane], v1 = xr[lane + 32], v2 = xr[lane + 64];
    float s = v0.x + v0.y + v0.z + v0.w + v1.x + v1.y + v1.z + v1.w + v2.x + v2.y + v2.z + v2.w;
    float s2 = v0.x*v0.x + v0.y*v0.y + v0.z*v0.z + v0.w*v0.w
             + v1.x*v1.x + v1.y*v1.y + v1.z*v1.z + v1.w*v1.w
             + v2.x*v2.x + v2.y*v2.y + v2.z*v2.z + v2.w*v2.w;
    #pragma unroll
    for (int o = 16; o; o >>= 1) {
        s  += __shfl_xor_sync(0xffffffffu, s, o);
        s2 += __shfl_xor_sync(0xffffffffu, s2, o);
    }
    float mu = s * (1.0f / CC);
    float var = s2 * (1.0f / CC) - mu * mu;
    float rstd = rsqrtf(var + 1e-6f);
    const float4* s4 = (const float4*)sc;
    const float4* b4 = (const float4*)bi;
    float4* orow = (float4*)(outp + (size_t)row * CC);
    #pragma unroll
    for (int c = 0; c < 3; c++) {
        float4 v = c == 0 ? v0 : (c == 1 ? v1 : v2);
        float4 g = s4[lane + c * 32], bb = b4[lane + c * 32], r;
        r.x = to_tf32((v.x - mu) * rstd * g.x + bb.x);
        r.y = to_tf32((v.y - mu) * rstd * g.y + bb.y);
        r.z = to_tf32((v.z - mu) * rstd * g.z + bb.z);
        r.w = to_tf32((v.w - mu) * rstd * g.w + bb.w);
        orow[lane + c * 32] = r;
    }
}

// ---------------- gelu ----------------
__device__ __forceinline__ float gelu_tanh(float x) {
    float x3 = x * x * x;
    return 0.5f * x * (1.0f + tanhf(0.7978845608028654f * (x + 0.044715f * x3)));
}

// ---------------- GEMM: C[M,N] = A[M,K] * B[N,K]^T ; CTA tile 128x384 ----------------
// K-stage = 16 (SW64): stage = A 8KB + 3x B 8KB = 32KB; 3 stages = 96KB (2 CTA/SM).
// 288 threads: warps 0-7 load, warp 8 lane 0 issues MMAs.
// Completion protocol: per-thread cp.async wait_group (scoreboard) + 1 arrive/warp
// (full count=8); done waited by lane0 only. 32x less mbarrier traffic than R8.
// EPI: 0 none | 2 gelu(acc+bias)+tf32round | 3 acc+bias+res | 4 acc+res
template <int EPI>
__global__ __launch_bounds__(288) void tc_gemm(const float* __restrict__ A,
                                               const float* __restrict__ B,
                                               const float* __restrict__ bias,
                                               const float* __restrict__ res,
                                               float* __restrict__ C,
                                               int K, int N) {
    extern __shared__ char smem[];
#if TC_OK
    uint32_t raw = smem_u32(smem);
    uint32_t base = (raw + 1023) & ~1023u;       // 3 stages x 32KB
    uint32_t ctrl = base + 98304;
    uint32_t fullb[3] = {ctrl, ctrl + 8, ctrl + 16};
    uint32_t doneb[3] = {ctrl + 24, ctrl + 32, ctrl + 40};
    uint32_t tptr = ctrl + 48;
    int tid = threadIdx.x, wid = tid >> 5, lane = tid & 31;
    int m0 = blockIdx.x << 7;
    int n0 = blockIdx.y * 384;
    int S = K >> 4;   // K stages of 16 (24 or 96)

    auto load_stage = [&](int s) {   // tid < 256 only; issue + commit, no arrive
        int b = s % 3;
        uint32_t st = base + b * 32768;
        int k0 = s << 4;
        #pragma unroll
        for (int i = 0; i < 8; i++) {
            int g = (i << 8) + tid;            // 0..2047 16B-chunks
            int tile = g >> 9;                 // 0 = A, 1..3 = B n-tiles
            int w = g & 511;
            int row = w >> 2;
            int cb  = (w & 3) << 4;
            uint32_t dst = st + (tile << 13) + SWZ64(row * 64 + cb);
            const float* src = (tile == 0)
                ? A + (size_t)(m0 + row) * K + k0 + (cb >> 2)
                : B + (size_t)(n0 + ((tile - 1) << 7) + row) * K + k0 + (cb >> 2);
            cp16(dst, src);
        }
        asm volatile("cp.async.commit_group;" ::: "memory");
    };

    if (wid == 0) {
        asm volatile("tcgen05.alloc.cta_group::1.sync.aligned.shared::cta.b32 [%0], %1;"
                     :: "r"(tptr), "r"(512) : "memory");
        asm volatile("tcgen05.relinquish_alloc_permit.cta_group::1.sync.aligned;");
    }
    if (tid == 0) {
        #pragma unroll
        for (int i = 0; i < 3; i++) {
            asm volatile("mbarrier.init.shared.b64 [%0], 8;" :: "r"(fullb[i]) : "memory");
            asm volatile("mbarrier.init.shared.b64 [%0], 1;" :: "r"(doneb[i]) : "memory");
        }
    }
    __syncthreads();
    uint32_t tmem;
    asm volatile("ld.shared.b32 %0, [%1];" : "=r"(tmem) : "r"(tptr));

    if (tid < 256) {
        load_stage(0);
        load_stage(1);
        load_stage(2);
        asm volatile("cp.async.wait_group 2;" ::: "memory");
        __syncwarp();
        if (lane == 0) mbar_arrive(fullb[0]);
    }

    if (wid == 8) {
        // ---- MMA issuer: gated only by full[b] ----
        if (lane == 0) {
            int fph[3] = {0, 0, 0};
            for (int s = 0; s < S; s++) {
                int b = s % 3;
                mbar_wait(fullb[b], fph[b]); fph[b] ^= 1;
                asm volatile("fence.proxy.async.shared::cta;" ::: "memory");
                uint32_t st = base + b * 32768;
                uint64_t ad = DESC_SW64 | ((uint64_t)(st >> 4) & 0x3FFF);
                #pragma unroll
                for (int nt = 0; nt < 3; nt++) {
                    uint64_t bd = DESC_SW64 |
                        ((uint64_t)((st + 8192 + nt * 8192) >> 4) & 0x3FFF);
                    #pragma unroll
                    for (int ks = 0; ks < 2; ks++)
                        mma_tf32_ss(tmem + nt * 128, ad + 2 * ks, bd + 2 * ks,
                                    IDESC_TF32, (s | ks) != 0);
                }
                asm volatile("tcgen05.commit.cta_group::1.mbarrier::arrive::one.shared::cluster.b64 [%0];"
                             :: "r"(doneb[b]) : "memory");
            }
        }
    } else {
        // ---- loaders: recycle buffers on done[b]; signal full via wait_group ----
        int dph[3] = {0, 0, 0};
        for (int s = 3; s < S; s++) {
            int b = s % 3;
            if (lane == 0) mbar_wait(doneb[b], dph[b]);
            dph[b] ^= 1;
            __syncwarp();
            load_stage(s);
            asm volatile("cp.async.wait_group 2;" ::: "memory");
            __syncwarp();
            if (lane == 0) mbar_arrive(fullb[(s - 2) % 3]);
        }
        asm volatile("cp.async.wait_group 1;" ::: "memory");
        __syncwarp();
        if (lane == 0) mbar_arrive(fullb[(S - 2) % 3]);
        asm volatile("cp.async.wait_group 0;" ::: "memory");
        __syncwarp();
        if (lane == 0) mbar_arrive(fullb[(S - 1) % 3]);
        int bl = (S - 1) % 3;
        if (lane == 0) mbar_wait(doneb[bl], dph[bl]);
        __syncwarp();
    }
    __syncthreads();

    asm volatile("tcgen05.fence::after_thread_sync;" ::: "memory");
    if (wid < 8) {
        int row = m0 + ((wid & 3) << 5) + lane;
        int colHalf = (wid >> 2) << 6;           // 0 or 64
        uint32_t toff = tmem + ((uint32_t)(wid & 3) << 21);
        #pragma unroll
        for (int nt = 0; nt < 3; nt++) {
            #pragma unroll
            for (int g = 0; g < 2; g++) {
                int col = nt * 128 + colHalf + g * 32;
                uint32_t r[32];
                LDTM_X32(r, toff + col);
                asm volatile("tcgen05.wait::ld.sync.aligned;" ::: "memory");
                float* crow = C + (size_t)row * N + n0 + col;
                const float4* rrow = (EPI == 3 || EPI == 4)
                    ? (const float4*)(res + (size_t)row * N + n0 + col) : nullptr;
                const float4* b4 = (EPI == 2 || EPI == 3)
                    ? (const float4*)(bias + n0 + col) : nullptr;
                #pragma unroll
                for (int j = 0; j < 32; j += 4) {
                    float4 v;
                    v.x = __uint_as_float(r[j + 0]);
                    v.y = __uint_as_float(r[j + 1]);
                    v.z = __uint_as_float(r[j + 2]);
                    v.w = __uint_as_float(r[j + 3]);
                    if (EPI == 2 || EPI == 3) {
                        float4 bb = b4[j >> 2];
                        v.x += bb.x; v.y += bb.y; v.z += bb.z; v.w += bb.w;
                    }
                    if (EPI == 2) {
                        v.x = to_tf32(gelu_tanh(v.x)); v.y = to_tf32(gelu_tanh(v.y));
                        v.z = to_tf32(gelu_tanh(v.z)); v.w = to_tf32(gelu_tanh(v.w));
                    }
                    if (EPI == 3 || EPI == 4) {
                        float4 rr = rrow[j >> 2];
                        v.x += rr.x; v.y += rr.y; v.z += rr.z; v.w += rr.w;
                    }
                    *(float4*)(crow + j) = v;
                }
            }
        }
    }
    __syncthreads();
    if (wid == 0)
        asm volatile("tcgen05.dealloc.cta_group::1.sync.aligned.b32 %0, %1;"
                     :: "r"(tmem), "r"(512));
#else
    // ---------- SIMT fallback (plain sm_103 target; never selected at runtime) ----------
    (void)smem;
    int tid = threadIdx.x;
    int m0 = blockIdx.x << 7;
    int n0 = blockIdx.y * 384;
    for (int e = tid; e < 128 * 384; e += 288) {
        int i = e / 384, j = e % 384;
        int row = m0 + i, coln = n0 + j;
        float acc = 0.0f;
        for (int k = 0; k < K; k++)
            acc += A[(size_t)row * K + k] * B[(size_t)coln * K + k];
        float v = acc;
        if (EPI == 2 || EPI == 3) v += bias[coln];
        if (EPI == 2) v = to_tf32(gelu_tanh(v));
        if (EPI == 3 || EPI == 4) v += res[(size_t)row * N + coln];
        C[(size_t)row * N + coln] = v;
    }
#endif
}

// ---------------- windowed attention: register-tiled, float4 ----------------
__global__ __launch_bounds__(224) void attn_kernel(const float* __restrict__ qkv,
                                                   const float* __restrict__ rpb,
                                                   float* __restrict__ o) {
    __shared__ float sQ[NT * 32];
    __shared__ float sK[NT * 36];
    __shared__ float sV[NT * 32];
    __shared__ float sS[NT * 52];
    __shared__ float sB[169];

    int w = blockIdx.x / HEADS, hh = blockIdx.x % HEADS;
    int tid = threadIdx.x, warp = tid >> 5, lane = tid & 31;
    const float* basep = qkv + (size_t)(w * NT) * (3 * CC) + hh * HD;

    for (int i = tid; i < NT * 8; i += 224) {
        int t = i >> 3, d4 = i & 7;
        const float4* p = (const float4*)(basep + (size_t)t * (3 * CC));
        *(float4*)&sQ[t * 32 + d4 * 4] = p[d4];
        *(float4*)&sK[t * 36 + d4 * 4] = p[96 + d4];
        *(float4*)&sV[t * 32 + d4 * 4] = p[192 + d4];
    }
    for (int i = tid; i < 169; i += 224) sB[i] = rpb[i * HEADS + hh];
    __syncthreads();

    const float scale = 0.17677669529663687f;
    int q0 = warp * 7;
    int k1 = lane, k2 = lane + 32;

    {
        float a0[7], a1[7];
        #pragma unroll
        for (int i = 0; i < 7; i++) { a0[i] = 0.0f; a1[i] = 0.0f; }
        #pragma unroll
        for (int d4 = 0; d4 < 8; d4++) {
            float4 kv1 = *(const float4*)&sK[k1 * 36 + d4 * 4];
            float4 kv2 = (k2 < NT) ? *(const float4*)&sK[k2 * 36 + d4 * 4]
                                   : make_float4(0.f, 0.f, 0.f, 0.f);
            #pragma unroll
            for (int i = 0; i < 7; i++) {
                float4 qv = *(const float4*)&sQ[(q0 + i) * 32 + d4 * 4];
                a0[i] += qv.x * kv1.x + qv.y * kv1.y + qv.z * kv1.z + qv.w * kv1.w;
                a1[i] += qv.x * kv2.x + qv.y * kv2.y + qv.z * kv2.z + qv.w * kv2.w;
            }
        }
        int k1y = k1 / WS, k1x = k1 - k1y * WS;
        int k2y = k2 / WS, k2x = k2 - k2y * WS;
        #pragma unroll
        for (int i = 0; i < 7; i++) {
            int q = q0 + i;
            int qy = q / WS, qx = q - qy * WS;
            sS[q * 52 + k1] = a0[i] * scale + sB[(qy - k1y + 6) * 13 + (qx - k1x + 6)];
            if (k2 < NT)
                sS[q * 52 + k2] = a1[i] * scale + sB[(qy - k2y + 6) * 13 + (qx - k2x + 6)];
        }
    }
    __syncthreads();

    #pragma unroll
    for (int i = 0; i < 7; i++) {
        int row = q0 + i;
        float v0 = sS[row * 52 + lane];
        float v1 = (lane < 17) ? sS[row * 52 + 32 + lane] : -INFINITY;
        float m = fmaxf(v0, v1);
        #pragma unroll
        for (int ofs = 16; ofs; ofs >>= 1) m = fmaxf(m, __shfl_xor_sync(0xffffffffu, m, ofs));
        float e0 = __expf(v0 - m);
        float e1 = (lane < 17) ? __expf(v1 - m) : 0.0f;
        float sum = e0 + e1;
        #pragma unroll
        for (int ofs = 16; ofs; ofs >>= 1) sum += __shfl_xor_sync(0xffffffffu, sum, ofs);
        float inv = 1.0f / sum;
        sS[row * 52 + lane] = e0 * inv;
        if (lane < 17) sS[row * 52 + 32 + lane] = e1 * inv;
    }
    __syncthreads();

    {
        float outv[7];
        #pragma unroll
        for (int i = 0; i < 7; i++) outv[i] = 0.0f;
        #pragma unroll
        for (int k4 = 0; k4 < 48; k4 += 4) {
            float vk0 = sV[(k4 + 0) * 32 + lane];
            float vk1 = sV[(k4 + 1) * 32 + lane];
            float vk2 = sV[(k4 + 2) * 32 + lane];
            float vk3 = sV[(k4 + 3) * 32 + lane];
            #pragma unroll
            for (int i = 0; i < 7; i++) {
                float4 sv = *(const float4*)&sS[(q0 + i) * 52 + k4];
                outv[i] += sv.x * vk0 + sv.y * vk1 + sv.z * vk2 + sv.w * vk3;
            }
        }
        float vkl = sV[48 * 32 + lane];
        #pragma unroll
        for (int i = 0; i < 7; i++) outv[i] += sS[(q0 + i) * 52 + 48] * vkl;
        #pragma unroll
        for (int i = 0; i < 7; i++)
            o[(size_t)(w * NT + q0 + i) * CC + hh * HD + lane] = to_tf32(outv[i]);
    }
}

// ---------------- launch ----------------
extern "C" void kernel_launch(void* const* d_in, const int* in_sizes, int n_in,
                              void* d_out, int out_size) {
    const float* x      = (const float*)d_in[0];
    const float* ln1_s  = (const float*)d_in[1];
    const float* ln1_b  = (const float*)d_in[2];
    const float* qkv_w  = (const float*)d_in[3];
    const float* rpb    = (const float*)d_in[4];
    const float* proj_w = (const float*)d_in[5];
    const float* ln2_s  = (const float*)d_in[6];
    const float* ln2_b  = (const float*)d_in[7];
    const float* mlp_w1 = (const float*)d_in[8];
    const float* mlp_b1 = (const float*)d_in[9];
    const float* mlp_w2 = (const float*)d_in[10];
    const float* mlp_b2 = (const float*)d_in[11];
    float* out = (float*)d_out;

    float *xw, *h, *qkv, *o, *hidden, *wT;
    cudaGetSymbolAddress((void**)&xw, g_xw);
    cudaGetSymbolAddress((void**)&h, g_h);
    cudaGetSymbolAddress((void**)&qkv, g_qkv);
    cudaGetSymbolAddress((void**)&o, g_o);
    cudaGetSymbolAddress((void**)&hidden, g_hidden);
    cudaGetSymbolAddress((void**)&wT, g_wT);

    const int SMEM_SZ = 1024 + 98304 + 64;
    cudaFuncSetAttribute(tc_gemm<0>, cudaFuncAttributeMaxDynamicSharedMemorySize, SMEM_SZ);
    cudaFuncSetAttribute(tc_gemm<2>, cudaFuncAttributeMaxDynamicSharedMemorySize, SMEM_SZ);
    cudaFuncSetAttribute(tc_gemm<3>, cudaFuncAttributeMaxDynamicSharedMemorySize, SMEM_SZ);
    cudaFuncSetAttribute(tc_gemm<4>, cudaFuncAttributeMaxDynamicSharedMemorySize, SMEM_SZ);

    transpose_all<<<dim3(1728, 2), dim3(32, 8)>>>(qkv_w, proj_w, mlp_w1, mlp_w2, wT);

    int nElem4 = MROWS * C4;
    win_partition<<<(nElem4 + 255) / 256, 256>>>((const float4*)x, (float4*)xw);

    const int MT = MROWS / 128;  // 392
    for (int l = 0; l < 2; l++) {
        float* wl = wT + (size_t)l * WT_LAYER;
        ln_kernel<<<MROWS / 8, 256>>>(xw, ln1_s + l * CC, ln1_b + l * CC, h);
        tc_gemm<0><<<dim3(MT, 3), 288, SMEM_SZ>>>(h, wl + OFF_QKV, nullptr, nullptr, qkv, 384, 1152);
        attn_kernel<<<NWIN * HEADS, 224>>>(qkv, rpb + (size_t)l * 169 * HEADS, o);
        tc_gemm<4><<<dim3(MT, 1), 288, SMEM_SZ>>>(o, wl + OFF_PROJ, nullptr, xw, xw, 384, 384);
        ln_kernel<<<MROWS / 8, 256>>>(xw, ln2_s + l * CC, ln2_b + l * CC, h);
        tc_gemm<2><<<dim3(MT, 4), 288, SMEM_SZ>>>(h, wl + OFF_W1, mlp_b1 + (size_t)l * 1536,
                                                   nullptr, hidden, 384, 1536);
        tc_gemm<3><<<dim3(MT, 1), 288, SMEM_SZ>>>(hidden, wl + OFF_W2, mlp_b2 + (size_t)l * 384,
                                                  xw, xw, 1536, 384);
    }

    win_unpartition<<<(nElem4 + 255) / 256, 256>>>((const float4*)xw, (float4*)out);
}

// round 11
// speedup vs baseline: 1.5853x; 1.4484x over previous
#include <cuda_runtime.h>
#include <math.h>
#include <stdint.h>

// ---------------- problem constants ----------------
#define CC 384
#define WS 7
#define NT 49
#define HEADS 12
#define HD 32
#define NWIN 1024
#define MROWS (NWIN * NT)   // 50176
#define C4 (CC / 4)

#if defined(__CUDA_ARCH_FEAT_SM103_ALL) || defined(__CUDA_ARCH_FEAT_SM100_ALL) || defined(__CUDA_ARCH_FEAT_SM101_ALL)
#define TC_OK 1
#else
#define TC_OK 0
#endif

// ---------------- scratch (device globals) ----------------
__device__ float g_xw[MROWS * CC];
__device__ float g_h[MROWS * CC];
__device__ float g_qkv[MROWS * 3 * CC];
__device__ float g_o[MROWS * CC];
__device__ float g_hidden[MROWS * 4 * CC];
#define WT_LAYER 1769472
__device__ float g_wT[2 * WT_LAYER];

#define OFF_QKV  0
#define OFF_PROJ 442368
#define OFF_W1   589824
#define OFF_W2   1179648

// ---------------- small helpers ----------------
__device__ __forceinline__ float to_tf32(float x) {
    uint32_t u;
    asm("cvt.rna.tf32.f32 %0, %1;" : "=r"(u) : "f"(x));
    return __uint_as_float(u);
}
__device__ __forceinline__ uint32_t smem_u32(const void* p) {
    uint32_t a;
    asm("{ .reg .u64 t; cvta.to.shared.u64 t, %1; cvt.u32.u64 %0, t; }" : "=r"(a) : "l"(p));
    return a;
}
__device__ __forceinline__ void cp16(uint32_t dst, const void* src) {
    asm volatile("cp.async.cg.shared.global [%0], [%1], 16;" :: "r"(dst), "l"(src));
}

// SW64 swizzle (64B rows): bits[5:4] ^= bits[8:7]
#define SWZ64(o) ((o) ^ (((o) >> 3) & 0x30))
// SW64 K-major smem descriptor: layout=4, version=1, SBO=32 (512B atom), LBO=1
#define DESC_SW64 ((4ull << 61) | (1ull << 46) | (32ull << 32) | (1ull << 16))
#define IDESC_TF32 0x08200910u    // f32 acc, tf32 in, N=128, M=128

#define STAGE_BYTES 16384          // A 8KB + B 8KB
#define NSTAGE 3

#if TC_OK
__device__ __forceinline__ void mbar_wait(uint32_t mb, int parity) {
    asm volatile(
        "{\n\t.reg .pred P;\n"
        "W%=:\n\t"
        "mbarrier.try_wait.parity.acquire.cta.shared::cta.b64 P, [%0], %1, 0x989680;\n\t"
        "@P bra D%=;\n\t"
        "bra W%=;\n"
        "D%=:\n\t}"
        :: "r"(mb), "r"(parity) : "memory");
}
__device__ __forceinline__ void mma_tf32_ss(uint32_t d, uint64_t a, uint64_t b,
                                            uint32_t idesc, uint32_t en) {
    asm volatile(
        "{\n\t.reg .pred p;\n\t"
        "setp.ne.u32 p, %4, 0;\n\t"
        "tcgen05.mma.cta_group::1.kind::tf32 [%0], %1, %2, %3, p;\n\t}"
        :: "r"(d), "l"(a), "l"(b), "r"(idesc), "r"(en) : "memory");
}
#define LDTM_X16(r, a) \
    asm volatile("tcgen05.ld.sync.aligned.32x32b.x16.b32 " \
        "{%0,%1,%2,%3,%4,%5,%6,%7,%8,%9,%10,%11,%12,%13,%14,%15}, [%16];" \
        : "=r"((r)[0]),"=r"((r)[1]),"=r"((r)[2]),"=r"((r)[3]), \
          "=r"((r)[4]),"=r"((r)[5]),"=r"((r)[6]),"=r"((r)[7]), \
          "=r"((r)[8]),"=r"((r)[9]),"=r"((r)[10]),"=r"((r)[11]), \
          "=r"((r)[12]),"=r"((r)[13]),"=r"((r)[14]),"=r"((r)[15]) \
        : "r"(a))
#endif

// ---------------- window partition / un-partition ----------------
__global__ void win_partition(const float4* __restrict__ x, float4* __restrict__ xw) {
    int t = blockIdx.x * blockDim.x + threadIdx.x;
    if (t >= MROWS * C4) return;
    int r = t / C4, c4 = t - r * C4;
    int w = r / NT, tt = r - w * NT;
    int b = w >> 6, wrem = w & 63, wy = wrem >> 3, wx = wrem & 7;
    int ty = tt / WS, tx = tt - ty * WS;
    int src = ((b * 56 + wy * WS + ty) * 56 + wx * WS + tx) * C4 + c4;
    xw[t] = x[src];
}
__global__ void win_unpartition(const float4* __restrict__ xw, float4* __restrict__ out) {
    int t = blockIdx.x * blockDim.x + threadIdx.x;
    if (t >= MROWS * C4) return;
    int r = t / C4, c4 = t - r * C4;
    int w = r / NT, tt = r - w * NT;
    int b = w >> 6, wrem = w & 63, wy = wrem >> 3, wx = wrem & 7;
    int ty = tt / WS, tx = tt - ty * WS;
    int dst = ((b * 56 + wy * WS + ty) * 56 + wx * WS + tx) * C4 + c4;
    out[dst] = xw[t];
}

// ---------------- fused weight transpose (all 4 weights, both layers) ----------------
__global__ void transpose_all(const float* __restrict__ qkv_w,
                              const float* __restrict__ proj_w,
                              const float* __restrict__ w1,
                              const float* __restrict__ w2,
                              float* __restrict__ wT) {
    __shared__ float t[32][33];
    int id = blockIdx.x, l = blockIdx.y;
    const float* src; size_t doff; int K, N, tn;
    if (id < 432)       { src = qkv_w  + (size_t)l*384*1152; doff = OFF_QKV;  K = 384;  N = 1152; tn = 36; }
    else if (id < 576)  { id -= 432; src = proj_w + (size_t)l*384*384;  doff = OFF_PROJ; K = 384;  N = 384;  tn = 12; }
    else if (id < 1152) { id -= 576; src = w1     + (size_t)l*384*1536; doff = OFF_W1;   K = 384;  N = 1536; tn = 48; }
    else                { id -= 1152; src = w2    + (size_t)l*1536*384; doff = OFF_W2;   K = 1536; N = 384;  tn = 12; }
    float* dst = wT + (size_t)l * WT_LAYER + doff;
    int k0 = (id / tn) * 32, n0 = (id % tn) * 32;
    int tx = threadIdx.x, ty = threadIdx.y;
    #pragma unroll
    for (int i = 0; i < 32; i += 8)
        t[ty + i][tx] = src[(size_t)(k0 + ty + i) * N + n0 + tx];
    __syncthreads();
    #pragma unroll
    for (int i = 0; i < 32; i += 8)
        dst[(size_t)(n0 + ty + i) * K + k0 + tx] = to_tf32(t[tx][ty + i]);
}

// ---------------- layernorm (rounds output to tf32) ----------------
__global__ __launch_bounds__(256) void ln_kernel(const float* __restrict__ xin,
                                                 const float* __restrict__ sc,
                                                 const float* __restrict__ bi,
                                                 float* __restrict__ outp) {
    int warp = threadIdx.x >> 5, lane = threadIdx.x & 31;
    int row = blockIdx.x * 8 + warp;
    const float4* xr = (const float4*)(xin + (size_t)row * CC);
    float4 v0 = xr[lane], v1 = xr[lane + 32], v2 = xr[lane + 64];
    float s = v0.x + v0.y + v0.z + v0.w + v1.x + v1.y + v1.z + v1.w + v2.x + v2.y + v2.z + v2.w;
    float s2 = v0.x*v0.x + v0.y*v0.y + v0.z*v0.z + v0.w*v0.w
             + v1.x*v1.x + v1.y*v1.y + v1.z*v1.z + v1.w*v1.w
             + v2.x*v2.x + v2.y*v2.y + v2.z*v2.z + v2.w*v2.w;
    #pragma unroll
    for (int o = 16; o; o >>= 1) {
        s  += __shfl_xor_sync(0xffffffffu, s, o);
        s2 += __shfl_xor_sync(0xffffffffu, s2, o);
    }
    float mu = s * (1.0f / CC);
    float var = s2 * (1.0f / CC) - mu * mu;
    float rstd = rsqrtf(var + 1e-6f);
    const float4* s4 = (const float4*)sc;
    const float4* b4 = (const float4*)bi;
    float4* orow = (float4*)(outp + (size_t)row * CC);
    #pragma unroll
    for (int c = 0; c < 3; c++) {
        float4 v = c == 0 ? v0 : (c == 1 ? v1 : v2);
        float4 g = s4[lane + c * 32], bb = b4[lane + c * 32], r;
        r.x = to_tf32((v.x - mu) * rstd * g.x + bb.x);
        r.y = to_tf32((v.y - mu) * rstd * g.y + bb.y);
        r.z = to_tf32((v.z - mu) * rstd * g.z + bb.z);
        r.w = to_tf32((v.w - mu) * rstd * g.w + bb.w);
        orow[lane + c * 32] = r;
    }
}

// ---------------- gelu ----------------
__device__ __forceinline__ float gelu_tanh(float x) {
    float x3 = x * x * x;
    return 0.5f * x * (1.0f + tanhf(0.7978845608028654f * (x + 0.044715f * x3)));
}

// ---------------- GEMM: C[M,N] = A[M,K] * B[N,K]^T ; CTA tile 128x128 ----------------
// K-stage = 16 (SW64): stage = A 8KB + B 8KB = 16KB; 3 stages = 48KB -> 4 CTA/SM
// (TMEM 4x128=512 cols, 4x288 threads). R8's proven mbarrier protocol.
// EPI: 0 none | 2 gelu(acc+bias)+tf32round | 3 acc+bias+res | 4 acc+res
template <int EPI>
__global__ __launch_bounds__(288, 4) void tc_gemm(const float* __restrict__ A,
                                                  const float* __restrict__ B,
                                                  const float* __restrict__ bias,
                                                  const float* __restrict__ res,
                                                  float* __restrict__ C,
                                                  int K, int N) {
    extern __shared__ char smem[];
#if TC_OK
    uint32_t raw = smem_u32(smem);
    uint32_t base = (raw + 1023) & ~1023u;       // 3 stages x 16KB
    uint32_t ctrl = base + NSTAGE * STAGE_BYTES;
    uint32_t fullb[3] = {ctrl, ctrl + 8, ctrl + 16};
    uint32_t doneb[3] = {ctrl + 24, ctrl + 32, ctrl + 40};
    uint32_t tptr = ctrl + 48;
    int tid = threadIdx.x, wid = tid >> 5, lane = tid & 31;
    int m0 = blockIdx.x << 7;
    int n0 = blockIdx.y << 7;
    int S = K >> 4;   // K stages of 16 (24 or 96)

    auto load_stage = [&](int s) {   // tid < 256 only
        int b = s % 3;
        uint32_t st = base + b * STAGE_BYTES;
        int k0 = s << 4;
        #pragma unroll
        for (int i = 0; i < 4; i++) {
            int g = (i << 8) + tid;            // 0..1023 16B-chunks
            int tile = g >> 9;                 // 0 = A, 1 = B
            int w = g & 511;
            int row = w >> 2;
            int cb  = (w & 3) << 4;
            uint32_t dst = st + (tile << 13) + SWZ64(row * 64 + cb);
            const float* src = (tile == 0)
                ? A + (size_t)(m0 + row) * K + k0 + (cb >> 2)
                : B + (size_t)(n0 + row) * K + k0 + (cb >> 2);
            cp16(dst, src);
        }
        asm volatile("cp.async.mbarrier.arrive.noinc.shared::cta.b64 [%0];"
                     :: "r"(fullb[b]) : "memory");
    };

    if (wid == 0) {
        asm volatile("tcgen05.alloc.cta_group::1.sync.aligned.shared::cta.b32 [%0], %1;"
                     :: "r"(tptr), "r"(128) : "memory");
        asm volatile("tcgen05.relinquish_alloc_permit.cta_group::1.sync.aligned;");
    }
    if (tid == 0) {
        #pragma unroll
        for (int i = 0; i < 3; i++) {
            asm volatile("mbarrier.init.shared.b64 [%0], 256;" :: "r"(fullb[i]) : "memory");
            asm volatile("mbarrier.init.shared.b64 [%0], 1;"   :: "r"(doneb[i]) : "memory");
        }
    }
    __syncthreads();
    uint32_t tmem;
    asm volatile("ld.shared.b32 %0, [%1];" : "=r"(tmem) : "r"(tptr));

    if (tid < 256) {
        load_stage(0);
        load_stage(1);
        load_stage(2);
    }

    if (wid == 8) {
        // ---- MMA issuer: gated only by full[b] ----
        if (lane == 0) {
            int fph[3] = {0, 0, 0};
            for (int s = 0; s < S; s++) {
                int b = s % 3;
                mbar_wait(fullb[b], fph[b]); fph[b] ^= 1;
                asm volatile("fence.proxy.async.shared::cta;" ::: "memory");
                uint32_t st = base + b * STAGE_BYTES;
                uint64_t ad = DESC_SW64 | ((uint64_t)(st >> 4) & 0x3FFF);
                uint64_t bd = DESC_SW64 | ((uint64_t)((st + 8192) >> 4) & 0x3FFF);
                #pragma unroll
                for (int ks = 0; ks < 2; ks++)
                    mma_tf32_ss(tmem, ad + 2 * ks, bd + 2 * ks,
                                IDESC_TF32, (s | ks) != 0);
                asm volatile("tcgen05.commit.cta_group::1.mbarrier::arrive::one.shared::cluster.b64 [%0];"
                             :: "r"(doneb[b]) : "memory");
            }
        }
    } else {
        // ---- loaders: gated only by done[b] (buffer recycling) ----
        int dph[3] = {0, 0, 0};
        for (int s = 3; s < S; s++) {
            int b = s % 3;
            mbar_wait(doneb[b], dph[b]); dph[b] ^= 1;
            load_stage(s);
        }
        int bl = (S - 1) % 3;
        mbar_wait(doneb[bl], dph[bl]);
    }
    __syncthreads();

    asm volatile("tcgen05.fence::after_thread_sync;" ::: "memory");
    if (wid < 8) {
        int row = m0 + ((wid & 3) << 5) + lane;
        int colbase = (wid >> 2) << 6;           // 0 or 64
        uint32_t toff = tmem + ((uint32_t)(wid & 3) << 21);
        #pragma unroll
        for (int g = 0; g < 4; g++) {
            int col = colbase + g * 16;
            uint32_t r[16];
            LDTM_X16(r, toff + col);
            asm volatile("tcgen05.wait::ld.sync.aligned;" ::: "memory");
            float* crow = C + (size_t)row * N + n0 + col;
            const float4* rrow = (EPI == 3 || EPI == 4)
                ? (const float4*)(res + (size_t)row * N + n0 + col) : nullptr;
            const float4* b4 = (EPI == 2 || EPI == 3)
                ? (const float4*)(bias + n0 + col) : nullptr;
            #pragma unroll
            for (int j = 0; j < 16; j += 4) {
                float4 v;
                v.x = __uint_as_float(r[j + 0]);
                v.y = __uint_as_float(r[j + 1]);
                v.z = __uint_as_float(r[j + 2]);
                v.w = __uint_as_float(r[j + 3]);
                if (EPI == 2 || EPI == 3) {
                    float4 bb = b4[j >> 2];
                    v.x += bb.x; v.y += bb.y; v.z += bb.z; v.w += bb.w;
                }
                if (EPI == 2) {
                    v.x = to_tf32(gelu_tanh(v.x)); v.y = to_tf32(gelu_tanh(v.y));
                    v.z = to_tf32(gelu_tanh(v.z)); v.w = to_tf32(gelu_tanh(v.w));
                }
                if (EPI == 3 || EPI == 4) {
                    float4 rr = rrow[j >> 2];
                    v.x += rr.x; v.y += rr.y; v.z += rr.z; v.w += rr.w;
                }
                *(float4*)(crow + j) = v;
            }
        }
    }
    __syncthreads();
    if (wid == 0)
        asm volatile("tcgen05.dealloc.cta_group::1.sync.aligned.b32 %0, %1;"
                     :: "r"(tmem), "r"(128));
#else
    // ---------- SIMT fallback (plain sm_103 target; never selected at runtime) ----------
    (void)smem;
    int tid = threadIdx.x;
    int m0 = blockIdx.x << 7;
    int n0 = blockIdx.y << 7;
    for (int e = tid; e < 128 * 128; e += 288) {
        int i = e >> 7, j = e & 127;
        int row = m0 + i, coln = n0 + j;
        float acc = 0.0f;
        for (int k = 0; k < K; k++)
            acc += A[(size_t)row * K + k] * B[(size_t)coln * K + k];
        float v = acc;
        if (EPI == 2 || EPI == 3) v += bias[coln];
        if (EPI == 2) v = to_tf32(gelu_tanh(v));
        if (EPI == 3 || EPI == 4) v += res[(size_t)row * N + coln];
        C[(size_t)row * N + coln] = v;
    }
#endif
}

// ---------------- windowed attention: register-tiled, float4 ----------------
__global__ __launch_bounds__(224) void attn_kernel(const float* __restrict__ qkv,
                                                   const float* __restrict__ rpb,
                                                   float* __restrict__ o) {
    __shared__ float sQ[NT * 32];
    __shared__ float sK[NT * 36];
    __shared__ float sV[NT * 32];
    __shared__ float sS[NT * 52];
    __shared__ float sB[169];

    int w = blockIdx.x / HEADS, hh = blockIdx.x % HEADS;
    int tid = threadIdx.x, warp = tid >> 5, lane = tid & 31;
    const float* basep = qkv + (size_t)(w * NT) * (3 * CC) + hh * HD;

    for (int i = tid; i < NT * 8; i += 224) {
        int t = i >> 3, d4 = i & 7;
        const float4* p = (const float4*)(basep + (size_t)t * (3 * CC));
        *(float4*)&sQ[t * 32 + d4 * 4] = p[d4];
        *(float4*)&sK[t * 36 + d4 * 4] = p[96 + d4];
        *(float4*)&sV[t * 32 + d4 * 4] = p[192 + d4];
    }
    for (int i = tid; i < 169; i += 224) sB[i] = rpb[i * HEADS + hh];
    __syncthreads();

    const float scale = 0.17677669529663687f;
    int q0 = warp * 7;
    int k1 = lane, k2 = lane + 32;

    {
        float a0[7], a1[7];
        #pragma unroll
        for (int i = 0; i < 7; i++) { a0[i] = 0.0f; a1[i] = 0.0f; }
        #pragma unroll
        for (int d4 = 0; d4 < 8; d4++) {
            float4 kv1 = *(const float4*)&sK[k1 * 36 + d4 * 4];
            float4 kv2 = (k2 < NT) ? *(const float4*)&sK[k2 * 36 + d4 * 4]
                                   : make_float4(0.f, 0.f, 0.f, 0.f);
            #pragma unroll
            for (int i = 0; i < 7; i++) {
                float4 qv = *(const float4*)&sQ[(q0 + i) * 32 + d4 * 4];
                a0[i] += qv.x * kv1.x + qv.y * kv1.y + qv.z * kv1.z + qv.w * kv1.w;
                a1[i] += qv.x * kv2.x + qv.y * kv2.y + qv.z * kv2.z + qv.w * kv2.w;
            }
        }
        int k1y = k1 / WS, k1x = k1 - k1y * WS;
        int k2y = k2 / WS, k2x = k2 - k2y * WS;
        #pragma unroll
        for (int i = 0; i < 7; i++) {
            int q = q0 + i;
            int qy = q / WS, qx = q - qy * WS;
            sS[q * 52 + k1] = a0[i] * scale + sB[(qy - k1y + 6) * 13 + (qx - k1x + 6)];
            if (k2 < NT)
                sS[q * 52 + k2] = a1[i] * scale + sB[(qy - k2y + 6) * 13 + (qx - k2x + 6)];
        }
    }
    __syncthreads();

    #pragma unroll
    for (int i = 0; i < 7; i++) {
        int row = q0 + i;
        float v0 = sS[row * 52 + lane];
        float v1 = (lane < 17) ? sS[row * 52 + 32 + lane] : -INFINITY;
        float m = fmaxf(v0, v1);
        #pragma unroll
        for (int ofs = 16; ofs; ofs >>= 1) m = fmaxf(m, __shfl_xor_sync(0xffffffffu, m, ofs));
        float e0 = __expf(v0 - m);
        float e1 = (lane < 17) ? __expf(v1 - m) : 0.0f;
        float sum = e0 + e1;
        #pragma unroll
        for (int ofs = 16; ofs; ofs >>= 1) sum += __shfl_xor_sync(0xffffffffu, sum, ofs);
        float inv = 1.0f / sum;
        sS[row * 52 + lane] = e0 * inv;
        if (lane < 17) sS[row * 52 + 32 + lane] = e1 * inv;
    }
    __syncthreads();

    {
        float outv[7];
        #pragma unroll
        for (int i = 0; i < 7; i++) outv[i] = 0.0f;
        #pragma unroll
        for (int k4 = 0; k4 < 48; k4 += 4) {
            float vk0 = sV[(k4 + 0) * 32 + lane];
            float vk1 = sV[(k4 + 1) * 32 + lane];
            float vk2 = sV[(k4 + 2) * 32 + lane];
            float vk3 = sV[(k4 + 3) * 32 + lane];
            #pragma unroll
            for (int i = 0; i < 7; i++) {
                float4 sv = *(const float4*)&sS[(q0 + i) * 52 + k4];
                outv[i] += sv.x * vk0 + sv.y * vk1 + sv.z * vk2 + sv.w * vk3;
            }
        }
        float vkl = sV[48 * 32 + lane];
        #pragma unroll
        for (int i = 0; i < 7; i++) outv[i] += sS[(q0 + i) * 52 + 48] * vkl;
        #pragma unroll
        for (int i = 0; i < 7; i++)
            o[(size_t)(w * NT + q0 + i) * CC + hh * HD + lane] = to_tf32(outv[i]);
    }
}

// ---------------- launch ----------------
extern "C" void kernel_launch(void* const* d_in, const int* in_sizes, int n_in,
                              void* d_out, int out_size) {
    const float* x      = (const float*)d_in[0];
    const float* ln1_s  = (const float*)d_in[1];
    const float* ln1_b  = (const float*)d_in[2];
    const float* qkv_w  = (const float*)d_in[3];
    const float* rpb    = (const float*)d_in[4];
    const float* proj_w = (const float*)d_in[5];
    const float* ln2_s  = (const float*)d_in[6];
    const float* ln2_b  = (const float*)d_in[7];
    const float* mlp_w1 = (const float*)d_in[8];
    const float* mlp_b1 = (const float*)d_in[9];
    const float* mlp_w2 = (const float*)d_in[10];
    const float* mlp_b2 = (const float*)d_in[11];
    float* out = (float*)d_out;

    float *xw, *h, *qkv, *o, *hidden, *wT;
    cudaGetSymbolAddress((void**)&xw, g_xw);
    cudaGetSymbolAddress((void**)&h, g_h);
    cudaGetSymbolAddress((void**)&qkv, g_qkv);
    cudaGetSymbolAddress((void**)&o, g_o);
    cudaGetSymbolAddress((void**)&hidden, g_hidden);
    cudaGetSymbolAddress((void**)&wT, g_wT);

    const int SMEM_SZ = 1024 + NSTAGE * STAGE_BYTES + 64;
    cudaFuncSetAttribute(tc_gemm<0>, cudaFuncAttributeMaxDynamicSharedMemorySize, SMEM_SZ);
    cudaFuncSetAttribute(tc_gemm<2>, cudaFuncAttributeMaxDynamicSharedMemorySize, SMEM_SZ);
    cudaFuncSetAttribute(tc_gemm<3>, cudaFuncAttributeMaxDynamicSharedMemorySize, SMEM_SZ);
    cudaFuncSetAttribute(tc_gemm<4>, cudaFuncAttributeMaxDynamicSharedMemorySize, SMEM_SZ);

    transpose_all<<<dim3(1728, 2), dim3(32, 8)>>>(qkv_w, proj_w, mlp_w1, mlp_w2, wT);

    int nElem4 = MROWS * C4;
    win_partition<<<(nElem4 + 255) / 256, 256>>>((const float4*)x, (float4*)xw);

    const int MT = MROWS / 128;  // 392
    for (int l = 0; l < 2; l++) {
        float* wl = wT + (size_t)l * WT_LAYER;
        ln_kernel<<<MROWS / 8, 256>>>(xw, ln1_s + l * CC, ln1_b + l * CC, h);
        tc_gemm<0><<<dim3(MT, 9), 288, SMEM_SZ>>>(h, wl + OFF_QKV, nullptr, nullptr, qkv, 384, 1152);
        attn_kernel<<<NWIN * HEADS, 224>>>(qkv, rpb + (size_t)l * 169 * HEADS, o);
        tc_gemm<4><<<dim3(MT, 3), 288, SMEM_SZ>>>(o, wl + OFF_PROJ, nullptr, xw, xw, 384, 384);
        ln_kernel<<<MROWS / 8, 256>>>(xw, ln2_s + l * CC, ln2_b + l * CC, h);
        tc_gemm<2><<<dim3(MT, 12), 288, SMEM_SZ>>>(h, wl + OFF_W1, mlp_b1 + (size_t)l * 1536,
                                                   nullptr, hidden, 384, 1536);
        tc_gemm<3><<<dim3(MT, 3), 288, SMEM_SZ>>>(hidden, wl + OFF_W2, mlp_b2 + (size_t)l * 384,
                                                  xw, xw, 1536, 384);
    }

    win_unpartition<<<(nElem4 + 255) / 256, 256>>>((const float4*)xw, (float4*)out);
}

// round 12
// speedup vs baseline: 1.6704x; 1.0537x over previous
#include <cuda_runtime.h>
#include <math.h>
#include <stdint.h>

// ---------------- problem constants ----------------
#define CC 384
#define WS 7
#define NT 49
#define HEADS 12
#define HD 32
#define NWIN 1024
#define MROWS (NWIN * NT)   // 50176
#define C4 (CC / 4)

#if defined(__CUDA_ARCH_FEAT_SM103_ALL) || defined(__CUDA_ARCH_FEAT_SM100_ALL) || defined(__CUDA_ARCH_FEAT_SM101_ALL)
#define TC_OK 1
#else
#define TC_OK 0
#endif

// ---------------- scratch (device globals) ----------------
__device__ float g_xw[MROWS * CC];
__device__ float g_h[MROWS * CC];
__device__ float g_qkv[MROWS * 3 * CC];
__device__ float g_o[MROWS * CC];
__device__ float g_hidden[MROWS * 4 * CC];
#define WT_LAYER 1769472
__device__ float g_wT[2 * WT_LAYER];

#define OFF_QKV  0
#define OFF_PROJ 442368
#define OFF_W1   589824
#define OFF_W2   1179648

// ---------------- small helpers ----------------
__device__ __forceinline__ float to_tf32(float x) {
    uint32_t u;
    asm("cvt.rna.tf32.f32 %0, %1;" : "=r"(u) : "f"(x));
    return __uint_as_float(u);
}
__device__ __forceinline__ uint32_t smem_u32(const void* p) {
    uint32_t a;
    asm("{ .reg .u64 t; cvta.to.shared.u64 t, %1; cvt.u32.u64 %0, t; }" : "=r"(a) : "l"(p));
    return a;
}
__device__ __forceinline__ void cp16(uint32_t dst, const void* src) {
    asm volatile("cp.async.cg.shared.global [%0], [%1], 16;" :: "r"(dst), "l"(src));
}
// windowed row -> image row permutation (both directions use the same map:
// window row r corresponds to image row perm(r))
__device__ __forceinline__ int perm_row(int r) {
    int w = r / NT, tt = r - w * NT;
    int b = w >> 6, wrem = w & 63, wy = wrem >> 3, wx = wrem & 7;
    int ty = tt / WS, tx = tt - ty * WS;
    return (b * 56 + wy * WS + ty) * 56 + wx * WS + tx;
}

// SW64 swizzle (64B rows): bits[5:4] ^= bits[8:7]
#define SWZ64(o) ((o) ^ (((o) >> 3) & 0x30))
// SW64 K-major smem descriptor: layout=4, version=1, SBO=32 (512B atom), LBO=1
#define DESC_SW64 ((4ull << 61) | (1ull << 46) | (32ull << 32) | (1ull << 16))
#define IDESC_TF32 0x08200910u    // f32 acc, tf32 in, N=128, M=128

#define STAGE_BYTES 16384          // A 8KB + B 8KB
#define NSTAGE 3

#if TC_OK
__device__ __forceinline__ void mbar_wait(uint32_t mb, int parity) {
    asm volatile(
        "{\n\t.reg .pred P;\n"
        "W%=:\n\t"
        "mbarrier.try_wait.parity.acquire.cta.shared::cta.b64 P, [%0], %1, 0x989680;\n\t"
        "@P bra D%=;\n\t"
        "bra W%=;\n"
        "D%=:\n\t}"
        :: "r"(mb), "r"(parity) : "memory");
}
__device__ __forceinline__ void mma_tf32_ss(uint32_t d, uint64_t a, uint64_t b,
                                            uint32_t idesc, uint32_t en) {
    asm volatile(
        "{\n\t.reg .pred p;\n\t"
        "setp.ne.u32 p, %4, 0;\n\t"
        "tcgen05.mma.cta_group::1.kind::tf32 [%0], %1, %2, %3, p;\n\t}"
        :: "r"(d), "l"(a), "l"(b), "r"(idesc), "r"(en) : "memory");
}
#define LDTM_X16(r, a) \
    asm volatile("tcgen05.ld.sync.aligned.32x32b.x16.b32 " \
        "{%0,%1,%2,%3,%4,%5,%6,%7,%8,%9,%10,%11,%12,%13,%14,%15}, [%16];" \
        : "=r"((r)[0]),"=r"((r)[1]),"=r"((r)[2]),"=r"((r)[3]), \
          "=r"((r)[4]),"=r"((r)[5]),"=r"((r)[6]),"=r"((r)[7]), \
          "=r"((r)[8]),"=r"((r)[9]),"=r"((r)[10]),"=r"((r)[11]), \
          "=r"((r)[12]),"=r"((r)[13]),"=r"((r)[14]),"=r"((r)[15]) \
        : "r"(a))
#endif

// ---------------- fused weight transpose (all 4 weights, both layers) ----------------
__global__ void transpose_all(const float* __restrict__ qkv_w,
                              const float* __restrict__ proj_w,
                              const float* __restrict__ w1,
                              const float* __restrict__ w2,
                              float* __restrict__ wT) {
    __shared__ float t[32][33];
    int id = blockIdx.x, l = blockIdx.y;
    const float* src; size_t doff; int K, N, tn;
    if (id < 432)       { src = qkv_w  + (size_t)l*384*1152; doff = OFF_QKV;  K = 384;  N = 1152; tn = 36; }
    else if (id < 576)  { id -= 432; src = proj_w + (size_t)l*384*384;  doff = OFF_PROJ; K = 384;  N = 384;  tn = 12; }
    else if (id < 1152) { id -= 576; src = w1     + (size_t)l*384*1536; doff = OFF_W1;   K = 384;  N = 1536; tn = 48; }
    else                { id -= 1152; src = w2    + (size_t)l*1536*384; doff = OFF_W2;   K = 1536; N = 384;  tn = 12; }
    float* dst = wT + (size_t)l * WT_LAYER + doff;
    int k0 = (id / tn) * 32, n0 = (id % tn) * 32;
    int tx = threadIdx.x, ty = threadIdx.y;
    #pragma unroll
    for (int i = 0; i < 32; i += 8)
        t[ty + i][tx] = src[(size_t)(k0 + ty + i) * N + n0 + tx];
    __syncthreads();
    #pragma unroll
    for (int i = 0; i < 32; i += 8)
        dst[(size_t)(n0 + ty + i) * K + k0 + tx] = to_tf32(t[tx][ty + i]);
}

// ---------------- layernorm (rounds output to tf32) ----------------
// PERM=1: read source rows through the window permutation (fuses win_partition)
template <int PERM>
__global__ __launch_bounds__(256) void ln_kernel(const float* __restrict__ xin,
                                                 const float* __restrict__ sc,
                                                 const float* __restrict__ bi,
                                                 float* __restrict__ outp) {
    int warp = threadIdx.x >> 5, lane = threadIdx.x & 31;
    int row = blockIdx.x * 8 + warp;
    int srow = PERM ? perm_row(row) : row;
    const float4* xr = (const float4*)(xin + (size_t)srow * CC);
    float4 v0 = xr[lane], v1 = xr[lane + 32], v2 = xr[lane + 64];
    float s = v0.x + v0.y + v0.z + v0.w + v1.x + v1.y + v1.z + v1.w + v2.x + v2.y + v2.z + v2.w;
    float s2 = v0.x*v0.x + v0.y*v0.y + v0.z*v0.z + v0.w*v0.w
             + v1.x*v1.x + v1.y*v1.y + v1.z*v1.z + v1.w*v1.w
             + v2.x*v2.x + v2.y*v2.y + v2.z*v2.z + v2.w*v2.w;
    #pragma unroll
    for (int o = 16; o; o >>= 1) {
        s  += __shfl_xor_sync(0xffffffffu, s, o);
        s2 += __shfl_xor_sync(0xffffffffu, s2, o);
    }
    float mu = s * (1.0f / CC);
    float var = s2 * (1.0f / CC) - mu * mu;
    float rstd = rsqrtf(var + 1e-6f);
    const float4* s4 = (const float4*)sc;
    const float4* b4 = (const float4*)bi;
    float4* orow = (float4*)(outp + (size_t)row * CC);
    #pragma unroll
    for (int c = 0; c < 3; c++) {
        float4 v = c == 0 ? v0 : (c == 1 ? v1 : v2);
        float4 g = s4[lane + c * 32], bb = b4[lane + c * 32], r;
        r.x = to_tf32((v.x - mu) * rstd * g.x + bb.x);
        r.y = to_tf32((v.y - mu) * rstd * g.y + bb.y);
        r.z = to_tf32((v.z - mu) * rstd * g.z + bb.z);
        r.w = to_tf32((v.w - mu) * rstd * g.w + bb.w);
        orow[lane + c * 32] = r;
    }
}

// ---------------- gelu ----------------
__device__ __forceinline__ float gelu_tanh(float x) {
    float x3 = x * x * x;
    return 0.5f * x * (1.0f + tanhf(0.7978845608028654f * (x + 0.044715f * x3)));
}

// ---------------- GEMM: C[M,N] = A[M,K] * B[N,K]^T ; CTA tile 128x128 ----------------
// K-stage = 16 (SW64): 3 stages = 48KB -> 4 CTA/SM (TMEM 4x128=512).
// Grid: blockIdx.x = N-tile (fastest) -> one wave covers all N-tiles of ~65 M-tiles,
// so A-tile re-reads hit L2 (A DRAM traffic /NT_tiles).
// EPI: 0 none | 2 gelu(acc+bias) | 3 acc+bias+res | 4 acc+res
//      5 acc+res(res rows permuted from image layout)   [layer0 proj]
//      6 acc+bias+res, store rows permuted to image layout [layer1 mlp2 -> out]
template <int EPI>
__global__ __launch_bounds__(288, 4) void tc_gemm(const float* __restrict__ A,
                                                  const float* __restrict__ B,
                                                  const float* __restrict__ bias,
                                                  const float* __restrict__ res,
                                                  float* __restrict__ C,
                                                  int K, int N) {
    extern __shared__ char smem[];
#if TC_OK
    uint32_t raw = smem_u32(smem);
    uint32_t base = (raw + 1023) & ~1023u;
    uint32_t ctrl = base + NSTAGE * STAGE_BYTES;
    uint32_t fullb[3] = {ctrl, ctrl + 8, ctrl + 16};
    uint32_t doneb[3] = {ctrl + 24, ctrl + 32, ctrl + 40};
    uint32_t tptr = ctrl + 48;
    int tid = threadIdx.x, wid = tid >> 5, lane = tid & 31;
    int m0 = blockIdx.y << 7;
    int n0 = blockIdx.x << 7;
    int S = K >> 4;

    auto load_stage = [&](int s) {   // tid < 256 only
        int b = s % 3;
        uint32_t st = base + b * STAGE_BYTES;
        int k0 = s << 4;
        #pragma unroll
        for (int i = 0; i < 4; i++) {
            int g = (i << 8) + tid;
            int tile = g >> 9;                 // 0 = A, 1 = B
            int w = g & 511;
            int row = w >> 2;
            int cb  = (w & 3) << 4;
            uint32_t dst = st + (tile << 13) + SWZ64(row * 64 + cb);
            const float* src = (tile == 0)
                ? A + (size_t)(m0 + row) * K + k0 + (cb >> 2)
                : B + (size_t)(n0 + row) * K + k0 + (cb >> 2);
            cp16(dst, src);
        }
        asm volatile("cp.async.mbarrier.arrive.noinc.shared::cta.b64 [%0];"
                     :: "r"(fullb[b]) : "memory");
    };

    if (wid == 0) {
        asm volatile("tcgen05.alloc.cta_group::1.sync.aligned.shared::cta.b32 [%0], %1;"
                     :: "r"(tptr), "r"(128) : "memory");
        asm volatile("tcgen05.relinquish_alloc_permit.cta_group::1.sync.aligned;");
    }
    if (tid == 0) {
        #pragma unroll
        for (int i = 0; i < 3; i++) {
            asm volatile("mbarrier.init.shared.b64 [%0], 256;" :: "r"(fullb[i]) : "memory");
            asm volatile("mbarrier.init.shared.b64 [%0], 1;"   :: "r"(doneb[i]) : "memory");
        }
    }
    __syncthreads();
    uint32_t tmem;
    asm volatile("ld.shared.b32 %0, [%1];" : "=r"(tmem) : "r"(tptr));

    if (tid < 256) {
        load_stage(0);
        load_stage(1);
        load_stage(2);
    }

    if (wid == 8) {
        if (lane == 0) {
            int fph[3] = {0, 0, 0};
            for (int s = 0; s < S; s++) {
                int b = s % 3;
                mbar_wait(fullb[b], fph[b]); fph[b] ^= 1;
                asm volatile("fence.proxy.async.shared::cta;" ::: "memory");
                uint32_t st = base + b * STAGE_BYTES;
                uint64_t ad = DESC_SW64 | ((uint64_t)(st >> 4) & 0x3FFF);
                uint64_t bd = DESC_SW64 | ((uint64_t)((st + 8192) >> 4) & 0x3FFF);
                #pragma unroll
                for (int ks = 0; ks < 2; ks++)
                    mma_tf32_ss(tmem, ad + 2 * ks, bd + 2 * ks,
                                IDESC_TF32, (s | ks) != 0);
                asm volatile("tcgen05.commit.cta_group::1.mbarrier::arrive::one.shared::cluster.b64 [%0];"
                             :: "r"(doneb[b]) : "memory");
            }
        }
    } else {
        int dph[3] = {0, 0, 0};
        for (int s = 3; s < S; s++) {
            int b = s % 3;
            mbar_wait(doneb[b], dph[b]); dph[b] ^= 1;
            load_stage(s);
        }
        int bl = (S - 1) % 3;
        mbar_wait(doneb[bl], dph[bl]);
    }
    __syncthreads();

    asm volatile("tcgen05.fence::after_thread_sync;" ::: "memory");
    if (wid < 8) {
        int row = m0 + ((wid & 3) << 5) + lane;
        int rrow_i = (EPI == 5) ? perm_row(row) : row;   // residual source row
        int srow_i = (EPI == 6) ? perm_row(row) : row;   // store destination row
        int colbase = (wid >> 2) << 6;           // 0 or 64
        uint32_t toff = tmem + ((uint32_t)(wid & 3) << 21);
        #pragma unroll
        for (int g = 0; g < 4; g++) {
            int col = colbase + g * 16;
            uint32_t r[16];
            LDTM_X16(r, toff + col);
            asm volatile("tcgen05.wait::ld.sync.aligned;" ::: "memory");
            float* crow = C + (size_t)srow_i * N + n0 + col;
            const float4* rrow = (EPI >= 3)
                ? (const float4*)(res + (size_t)rrow_i * N + n0 + col) : nullptr;
            const float4* b4 = (EPI == 2 || EPI == 3 || EPI == 6)
                ? (const float4*)(bias + n0 + col) : nullptr;
            #pragma unroll
            for (int j = 0; j < 16; j += 4) {
                float4 v;
                v.x = __uint_as_float(r[j + 0]);
                v.y = __uint_as_float(r[j + 1]);
                v.z = __uint_as_float(r[j + 2]);
                v.w = __uint_as_float(r[j + 3]);
                if (EPI == 2 || EPI == 3 || EPI == 6) {
                    float4 bb = b4[j >> 2];
                    v.x += bb.x; v.y += bb.y; v.z += bb.z; v.w += bb.w;
                }
                if (EPI == 2) {
                    v.x = to_tf32(gelu_tanh(v.x)); v.y = to_tf32(gelu_tanh(v.y));
                    v.z = to_tf32(gelu_tanh(v.z)); v.w = to_tf32(gelu_tanh(v.w));
                }
                if (EPI >= 3) {
                    float4 rr = rrow[j >> 2];
                    v.x += rr.x; v.y += rr.y; v.z += rr.z; v.w += rr.w;
                }
                *(float4*)(crow + j) = v;
            }
        }
    }
    __syncthreads();
    if (wid == 0)
        asm volatile("tcgen05.dealloc.cta_group::1.sync.aligned.b32 %0, %1;"
                     :: "r"(tmem), "r"(128));
#else
    // ---------- SIMT fallback (plain sm_103 target; never selected at runtime) ----------
    (void)smem;
    int tid = threadIdx.x;
    int m0 = blockIdx.y << 7;
    int n0 = blockIdx.x << 7;
    for (int e = tid; e < 128 * 128; e += 288) {
        int i = e >> 7, j = e & 127;
        int row = m0 + i, coln = n0 + j;
        int rrow_i = (EPI == 5) ? perm_row(row) : row;
        int srow_i = (EPI == 6) ? perm_row(row) : row;
        float acc = 0.0f;
        for (int k = 0; k < K; k++)
            acc += A[(size_t)row * K + k] * B[(size_t)coln * K + k];
        float v = acc;
        if (EPI == 2 || EPI == 3 || EPI == 6) v += bias[coln];
        if (EPI == 2) v = to_tf32(gelu_tanh(v));
        if (EPI >= 3) v += res[(size_t)rrow_i * N + coln];
        C[(size_t)srow_i * N + coln] = v;
    }
#endif
}

// ---------------- windowed attention: register-tiled, float4 ----------------
__global__ __launch_bounds__(224) void attn_kernel(const float* __restrict__ qkv,
                                                   const float* __restrict__ rpb,
                                                   float* __restrict__ o) {
    __shared__ float sQ[NT * 32];
    __shared__ float sK[NT * 36];
    __shared__ float sV[NT * 32];
    __shared__ float sS[NT * 52];
    __shared__ float sB[169];

    int w = blockIdx.x / HEADS, hh = blockIdx.x % HEADS;
    int tid = threadIdx.x, warp = tid >> 5, lane = tid & 31;
    const float* basep = qkv + (size_t)(w * NT) * (3 * CC) + hh * HD;

    for (int i = tid; i < NT * 8; i += 224) {
        int t = i >> 3, d4 = i & 7;
        const float4* p = (const float4*)(basep + (size_t)t * (3 * CC));
        *(float4*)&sQ[t * 32 + d4 * 4] = p[d4];
        *(float4*)&sK[t * 36 + d4 * 4] = p[96 + d4];
        *(float4*)&sV[t * 32 + d4 * 4] = p[192 + d4];
    }
    for (int i = tid; i < 169; i += 224) sB[i] = rpb[i * HEADS + hh];
    __syncthreads();

    const float scale = 0.17677669529663687f;
    int q0 = warp * 7;
    int k1 = lane, k2 = lane + 32;

    {
        float a0[7], a1[7];
        #pragma unroll
        for (int i = 0; i < 7; i++) { a0[i] = 0.0f; a1[i] = 0.0f; }
        #pragma unroll
        for (int d4 = 0; d4 < 8; d4++) {
            float4 kv1 = *(const float4*)&sK[k1 * 36 + d4 * 4];
            float4 kv2 = (k2 < NT) ? *(const float4*)&sK[k2 * 36 + d4 * 4]
                                   : make_float4(0.f, 0.f, 0.f, 0.f);
            #pragma unroll
            for (int i = 0; i < 7; i++) {
                float4 qv = *(const float4*)&sQ[(q0 + i) * 32 + d4 * 4];
                a0[i] += qv.x * kv1.x + qv.y * kv1.y + qv.z * kv1.z + qv.w * kv1.w;
                a1[i] += qv.x * kv2.x + qv.y * kv2.y + qv.z * kv2.z + qv.w * kv2.w;
            }
        }
        int k1y = k1 / WS, k1x = k1 - k1y * WS;
        int k2y = k2 / WS, k2x = k2 - k2y * WS;
        #pragma unroll
        for (int i = 0; i < 7; i++) {
            int q = q0 + i;
            int qy = q / WS, qx = q - qy * WS;
            sS[q * 52 + k1] = a0[i] * scale + sB[(qy - k1y + 6) * 13 + (qx - k1x + 6)];
            if (k2 < NT)
                sS[q * 52 + k2] = a1[i] * scale + sB[(qy - k2y + 6) * 13 + (qx - k2x + 6)];
        }
    }
    __syncthreads();

    #pragma unroll
    for (int i = 0; i < 7; i++) {
        int row = q0 + i;
        float v0 = sS[row * 52 + lane];
        float v1 = (lane < 17) ? sS[row * 52 + 32 + lane] : -INFINITY;
        float m = fmaxf(v0, v1);
        #pragma unroll
        for (int ofs = 16; ofs; ofs >>= 1) m = fmaxf(m, __shfl_xor_sync(0xffffffffu, m, ofs));
        float e0 = __expf(v0 - m);
        float e1 = (lane < 17) ? __expf(v1 - m) : 0.0f;
        float sum = e0 + e1;
        #pragma unroll
        for (int ofs = 16; ofs; ofs >>= 1) sum += __shfl_xor_sync(0xffffffffu, sum, ofs);
        float inv = 1.0f / sum;
        sS[row * 52 + lane] = e0 * inv;
        if (lane < 17) sS[row * 52 + 32 + lane] = e1 * inv;
    }
    __syncthreads();

    {
        float outv[7];
        #pragma unroll
        for (int i = 0; i < 7; i++) outv[i] = 0.0f;
        #pragma unroll
        for (int k4 = 0; k4 < 48; k4 += 4) {
            float vk0 = sV[(k4 + 0) * 32 + lane];
            float vk1 = sV[(k4 + 1) * 32 + lane];
            float vk2 = sV[(k4 + 2) * 32 + lane];
            float vk3 = sV[(k4 + 3) * 32 + lane];
            #pragma unroll
            for (int i = 0; i < 7; i++) {
                float4 sv = *(const float4*)&sS[(q0 + i) * 52 + k4];
                outv[i] += sv.x * vk0 + sv.y * vk1 + sv.z * vk2 + sv.w * vk3;
            }
        }
        float vkl = sV[48 * 32 + lane];
        #pragma unroll
        for (int i = 0; i < 7; i++) outv[i] += sS[(q0 + i) * 52 + 48] * vkl;
        #pragma unroll
        for (int i = 0; i < 7; i++)
            o[(size_t)(w * NT + q0 + i) * CC + hh * HD + lane] = to_tf32(outv[i]);
    }
}

// ---------------- launch ----------------
extern "C" void kernel_launch(void* const* d_in, const int* in_sizes, int n_in,
                              void* d_out, int out_size) {
    const float* x      = (const float*)d_in[0];
    const float* ln1_s  = (const float*)d_in[1];
    const float* ln1_b  = (const float*)d_in[2];
    const float* qkv_w  = (const float*)d_in[3];
    const float* rpb    = (const float*)d_in[4];
    const float* proj_w = (const float*)d_in[5];
    const float* ln2_s  = (const float*)d_in[6];
    const float* ln2_b  = (const float*)d_in[7];
    const float* mlp_w1 = (const float*)d_in[8];
    const float* mlp_b1 = (const float*)d_in[9];
    const float* mlp_w2 = (const float*)d_in[10];
    const float* mlp_b2 = (const float*)d_in[11];
    float* out = (float*)d_out;

    float *xw, *h, *qkv, *o, *hidden, *wT;
    cudaGetSymbolAddress((void**)&xw, g_xw);
    cudaGetSymbolAddress((void**)&h, g_h);
    cudaGetSymbolAddress((void**)&qkv, g_qkv);
    cudaGetSymbolAddress((void**)&o, g_o);
    cudaGetSymbolAddress((void**)&hidden, g_hidden);
    cudaGetSymbolAddress((void**)&wT, g_wT);

    const int SMEM_SZ = 1024 + NSTAGE * STAGE_BYTES + 64;
    cudaFuncSetAttribute(tc_gemm<0>, cudaFuncAttributeMaxDynamicSharedMemorySize, SMEM_SZ);
    cudaFuncSetAttribute(tc_gemm<2>, cudaFuncAttributeMaxDynamicSharedMemorySize, SMEM_SZ);
    cudaFuncSetAttribute(tc_gemm<3>, cudaFuncAttributeMaxDynamicSharedMemorySize, SMEM_SZ);
    cudaFuncSetAttribute(tc_gemm<4>, cudaFuncAttributeMaxDynamicSharedMemorySize, SMEM_SZ);
    cudaFuncSetAttribute(tc_gemm<5>, cudaFuncAttributeMaxDynamicSharedMemorySize, SMEM_SZ);
    cudaFuncSetAttribute(tc_gemm<6>, cudaFuncAttributeMaxDynamicSharedMemorySize, SMEM_SZ);

    transpose_all<<<dim3(1728, 2), dim3(32, 8)>>>(qkv_w, proj_w, mlp_w1, mlp_w2, wT);

    const int MT = MROWS / 128;  // 392
    for (int l = 0; l < 2; l++) {
        float* wl = wT + (size_t)l * WT_LAYER;
        if (l == 0)
            ln_kernel<1><<<MROWS / 8, 256>>>(x, ln1_s, ln1_b, h);
        else
            ln_kernel<0><<<MROWS / 8, 256>>>(xw, ln1_s + CC, ln1_b + CC, h);
        tc_gemm<0><<<dim3(9, MT), 288, SMEM_SZ>>>(h, wl + OFF_QKV, nullptr, nullptr, qkv, 384, 1152);
        attn_kernel<<<NWIN * HEADS, 224>>>(qkv, rpb + (size_t)l * 169 * HEADS, o);
        if (l == 0)
            tc_gemm<5><<<dim3(3, MT), 288, SMEM_SZ>>>(o, wl + OFF_PROJ, nullptr, x, xw, 384, 384);
        else
            tc_gemm<4><<<dim3(3, MT), 288, SMEM_SZ>>>(o, wl + OFF_PROJ, nullptr, xw, xw, 384, 384);
        ln_kernel<0><<<MROWS / 8, 256>>>(xw, ln2_s + l * CC, ln2_b + l * CC, h);
        tc_gemm<2><<<dim3(12, MT), 288, SMEM_SZ>>>(h, wl + OFF_W1, mlp_b1 + (size_t)l * 1536,
                                                   nullptr, hidden, 384, 1536);
        if (l == 0)
            tc_gemm<3><<<dim3(3, MT), 288, SMEM_SZ>>>(hidden, wl + OFF_W2, mlp_b2,
                                                      xw, xw, 1536, 384);
        else
            tc_gemm<6><<<dim3(3, MT), 288, SMEM_SZ>>>(hidden, wl + OFF_W2, mlp_b2 + 384,
                                                      xw, out, 1536, 384);
    }
}

// round 13
// speedup vs baseline: 1.8816x; 1.1264x over previous
#include <cuda_runtime.h>
#include <cuda_bf16.h>
#include <math.h>
#include <stdint.h>

// ---------------- problem constants ----------------
#define CC 384
#define WS 7
#define NT 49
#define HEADS 12
#define HD 32
#define NWIN 1024
#define MROWS (NWIN * NT)   // 50176
#define C4 (CC / 4)

#if defined(__CUDA_ARCH_FEAT_SM103_ALL) || defined(__CUDA_ARCH_FEAT_SM100_ALL) || defined(__CUDA_ARCH_FEAT_SM101_ALL)
#define TC_OK 1
#else
#define TC_OK 0
#endif

// ---------------- scratch (device globals) ----------------
__device__ float g_xw[MROWS * CC];                 // residual stream (fp32)
__device__ __nv_bfloat16 g_h[MROWS * CC];          // LN output (bf16)
__device__ float g_qkv[MROWS * 3 * CC];            // qkv (fp32, feeds attention)
__device__ __nv_bfloat16 g_o[MROWS * CC];          // attention output (bf16)
__device__ __nv_bfloat16 g_hidden[MROWS * 4 * CC]; // gelu output (bf16)
#define WT_LAYER 1769472
__device__ __nv_bfloat16 g_wT[2 * WT_LAYER];       // transposed weights (bf16)

#define OFF_QKV  0
#define OFF_PROJ 442368
#define OFF_W1   589824
#define OFF_W2   1179648

// ---------------- small helpers ----------------
__device__ __forceinline__ uint32_t smem_u32(const void* p) {
    uint32_t a;
    asm("{ .reg .u64 t; cvta.to.shared.u64 t, %1; cvt.u32.u64 %0, t; }" : "=r"(a) : "l"(p));
    return a;
}
__device__ __forceinline__ void cp16(uint32_t dst, const void* src) {
    asm volatile("cp.async.cg.shared.global [%0], [%1], 16;" :: "r"(dst), "l"(src));
}
// windowed row r <-> image row perm(r)
__device__ __forceinline__ int perm_row(int r) {
    int w = r / NT, tt = r - w * NT;
    int b = w >> 6, wrem = w & 63, wy = wrem >> 3, wx = wrem & 7;
    int ty = tt / WS, tx = tt - ty * WS;
    return (b * 56 + wy * WS + ty) * 56 + wx * WS + tx;
}

// SW64 swizzle (64B rows): bits[5:4] ^= bits[8:7]
#define SWZ64(o) ((o) ^ (((o) >> 3) & 0x30))
// SW64 K-major smem descriptor: layout=4, version=1, SBO=32 (512B atom), LBO=1
#define DESC_SW64 ((4ull << 61) | (1ull << 46) | (32ull << 32) | (1ull << 16))
// idesc kind::f16 bf16: dtype=F32(1<<4), atype=BF16(1<<7), btype=BF16(1<<10),
// N=128 (16<<17), M=128 (8<<24)
#define IDESC_BF16 0x08200490u

#define STAGE_BYTES 16384          // A 8KB + B 8KB  (K-chunk = 32 bf16 per 64B row)
#define NSTAGE 3

#if TC_OK
__device__ __forceinline__ void mbar_wait(uint32_t mb, int parity) {
    asm volatile(
        "{\n\t.reg .pred P;\n"
        "W%=:\n\t"
        "mbarrier.try_wait.parity.acquire.cta.shared::cta.b64 P, [%0], %1, 0x989680;\n\t"
        "@P bra D%=;\n\t"
        "bra W%=;\n"
        "D%=:\n\t}"
        :: "r"(mb), "r"(parity) : "memory");
}
__device__ __forceinline__ void mma_bf16_ss(uint32_t d, uint64_t a, uint64_t b,
                                            uint32_t idesc, uint32_t en) {
    asm volatile(
        "{\n\t.reg .pred p;\n\t"
        "setp.ne.u32 p, %4, 0;\n\t"
        "tcgen05.mma.cta_group::1.kind::f16 [%0], %1, %2, %3, p;\n\t}"
        :: "r"(d), "l"(a), "l"(b), "r"(idesc), "r"(en) : "memory");
}
#define LDTM_X16(r, a) \
    asm volatile("tcgen05.ld.sync.aligned.32x32b.x16.b32 " \
        "{%0,%1,%2,%3,%4,%5,%6,%7,%8,%9,%10,%11,%12,%13,%14,%15}, [%16];" \
        : "=r"((r)[0]),"=r"((r)[1]),"=r"((r)[2]),"=r"((r)[3]), \
          "=r"((r)[4]),"=r"((r)[5]),"=r"((r)[6]),"=r"((r)[7]), \
          "=r"((r)[8]),"=r"((r)[9]),"=r"((r)[10]),"=r"((r)[11]), \
          "=r"((r)[12]),"=r"((r)[13]),"=r"((r)[14]),"=r"((r)[15]) \
        : "r"(a))
#endif

// ---------------- fused weight transpose -> bf16 K-major ----------------
__global__ void transpose_all(const float* __restrict__ qkv_w,
                              const float* __restrict__ proj_w,
                              const float* __restrict__ w1,
                              const float* __restrict__ w2,
                              __nv_bfloat16* __restrict__ wT) {
    __shared__ float t[32][33];
    int id = blockIdx.x, l = blockIdx.y;
    const float* src; size_t doff; int K, N, tn;
    if (id < 432)       { src = qkv_w  + (size_t)l*384*1152; doff = OFF_QKV;  K = 384;  N = 1152; tn = 36; }
    else if (id < 576)  { id -= 432; src = proj_w + (size_t)l*384*384;  doff = OFF_PROJ; K = 384;  N = 384;  tn = 12; }
    else if (id < 1152) { id -= 576; src = w1     + (size_t)l*384*1536; doff = OFF_W1;   K = 384;  N = 1536; tn = 48; }
    else                { id -= 1152; src = w2    + (size_t)l*1536*384; doff = OFF_W2;   K = 1536; N = 384;  tn = 12; }
    __nv_bfloat16* dst = wT + (size_t)l * WT_LAYER + doff;
    int k0 = (id / tn) * 32, n0 = (id % tn) * 32;
    int tx = threadIdx.x, ty = threadIdx.y;
    #pragma unroll
    for (int i = 0; i < 32; i += 8)
        t[ty + i][tx] = src[(size_t)(k0 + ty + i) * N + n0 + tx];
    __syncthreads();
    #pragma unroll
    for (int i = 0; i < 32; i += 8)
        dst[(size_t)(n0 + ty + i) * K + k0 + tx] = __float2bfloat16(t[tx][ty + i]);
}

// ---------------- layernorm: fp32 in -> bf16 out ----------------
// PERM=1: read source rows through the window permutation (fuses win_partition)
template <int PERM>
__global__ __launch_bounds__(256) void ln_kernel(const float* __restrict__ xin,
                                                 const float* __restrict__ sc,
                                                 const float* __restrict__ bi,
                                                 __nv_bfloat16* __restrict__ outp) {
    int warp = threadIdx.x >> 5, lane = threadIdx.x & 31;
    int row = blockIdx.x * 8 + warp;
    int srow = PERM ? perm_row(row) : row;
    const float4* xr = (const float4*)(xin + (size_t)srow * CC);
    float4 v0 = xr[lane], v1 = xr[lane + 32], v2 = xr[lane + 64];
    float s = v0.x + v0.y + v0.z + v0.w + v1.x + v1.y + v1.z + v1.w + v2.x + v2.y + v2.z + v2.w;
    float s2 = v0.x*v0.x + v0.y*v0.y + v0.z*v0.z + v0.w*v0.w
             + v1.x*v1.x + v1.y*v1.y + v1.z*v1.z + v1.w*v1.w
             + v2.x*v2.x + v2.y*v2.y + v2.z*v2.z + v2.w*v2.w;
    #pragma unroll
    for (int o = 16; o; o >>= 1) {
        s  += __shfl_xor_sync(0xffffffffu, s, o);
        s2 += __shfl_xor_sync(0xffffffffu, s2, o);
    }
    float mu = s * (1.0f / CC);
    float var = s2 * (1.0f / CC) - mu * mu;
    float rstd = rsqrtf(var + 1e-6f);
    const float4* s4 = (const float4*)sc;
    const float4* b4 = (const float4*)bi;
    __nv_bfloat16* orow = outp + (size_t)row * CC;
    #pragma unroll
    for (int c = 0; c < 3; c++) {
        float4 v = c == 0 ? v0 : (c == 1 ? v1 : v2);
        float4 g = s4[lane + c * 32], bb = b4[lane + c * 32];
        float rx = (v.x - mu) * rstd * g.x + bb.x;
        float ry = (v.y - mu) * rstd * g.y + bb.y;
        float rz = (v.z - mu) * rstd * g.z + bb.z;
        float rw = (v.w - mu) * rstd * g.w + bb.w;
        __nv_bfloat162 p0 = __floats2bfloat162_rn(rx, ry);
        __nv_bfloat162 p1 = __floats2bfloat162_rn(rz, rw);
        uint2 pk;
        pk.x = *(uint32_t*)&p0;
        pk.y = *(uint32_t*)&p1;
        *(uint2*)(orow + (lane + c * 32) * 4) = pk;
    }
}

// ---------------- gelu ----------------
__device__ __forceinline__ float gelu_tanh(float x) {
    float x3 = x * x * x;
    return 0.5f * x * (1.0f + tanhf(0.7978845608028654f * (x + 0.044715f * x3)));
}

// ---------------- GEMM: C[M,N] = A[M,K] * B[N,K]^T ; bf16 in, fp32 acc ----------------
// CTA tile 128x128, K-stage = 32 (SW64 64B rows of bf16): 3 stages = 48KB -> 4 CTA/SM.
// Grid: blockIdx.x = N-tile (fastest) for A reuse in L2.
// EPI: 0 qkv (fp32 out) | 2 gelu+bias -> bf16 out | 3 acc+bias+res (fp32)
//      4 acc+res | 5 acc+res(perm rows) | 6 acc+bias+res, store rows permuted
template <int EPI>
__global__ __launch_bounds__(288, 4) void tc_gemm(const __nv_bfloat16* __restrict__ A,
                                                  const __nv_bfloat16* __restrict__ B,
                                                  const float* __restrict__ bias,
                                                  const float* __restrict__ res,
                                                  float* __restrict__ C,
                                                  int K, int N) {
    extern __shared__ char smem[];
#if TC_OK
    uint32_t raw = smem_u32(smem);
    uint32_t base = (raw + 1023) & ~1023u;
    uint32_t ctrl = base + NSTAGE * STAGE_BYTES;
    uint32_t fullb[3] = {ctrl, ctrl + 8, ctrl + 16};
    uint32_t doneb[3] = {ctrl + 24, ctrl + 32, ctrl + 40};
    uint32_t tptr = ctrl + 48;
    int tid = threadIdx.x, wid = tid >> 5, lane = tid & 31;
    int m0 = blockIdx.y << 7;
    int n0 = blockIdx.x << 7;
    int S = K >> 5;   // K stages of 32 (12 or 48)

    auto load_stage = [&](int s) {   // tid < 256 only
        int b = s % 3;
        uint32_t st = base + b * STAGE_BYTES;
        int k0 = s << 5;
        #pragma unroll
        for (int i = 0; i < 4; i++) {
            int g = (i << 8) + tid;            // 0..1023 16B-chunks
            int tile = g >> 9;                 // 0 = A, 1 = B
            int w = g & 511;
            int row = w >> 2;
            int cb  = (w & 3) << 4;            // byte col in 64B row
            uint32_t dst = st + (tile << 13) + SWZ64(row * 64 + cb);
            const __nv_bfloat16* src = (tile == 0)
                ? A + (size_t)(m0 + row) * K + k0 + (cb >> 1)
                : B + (size_t)(n0 + row) * K + k0 + (cb >> 1);
            cp16(dst, src);
        }
        asm volatile("cp.async.mbarrier.arrive.noinc.shared::cta.b64 [%0];"
                     :: "r"(fullb[b]) : "memory");
    };

    if (wid == 0) {
        asm volatile("tcgen05.alloc.cta_group::1.sync.aligned.shared::cta.b32 [%0], %1;"
                     :: "r"(tptr), "r"(128) : "memory");
        asm volatile("tcgen05.relinquish_alloc_permit.cta_group::1.sync.aligned;");
    }
    if (tid == 0) {
        #pragma unroll
        for (int i = 0; i < 3; i++) {
            asm volatile("mbarrier.init.shared.b64 [%0], 256;" :: "r"(fullb[i]) : "memory");
            asm volatile("mbarrier.init.shared.b64 [%0], 1;"   :: "r"(doneb[i]) : "memory");
        }
    }
    __syncthreads();
    uint32_t tmem;
    asm volatile("ld.shared.b32 %0, [%1];" : "=r"(tmem) : "r"(tptr));

    if (tid < 256) {
        load_stage(0);
        load_stage(1);
        load_stage(2);
    }

    if (wid == 8) {
        if (lane == 0) {
            int fph[3] = {0, 0, 0};
            for (int s = 0; s < S; s++) {
                int b = s % 3;
                mbar_wait(fullb[b], fph[b]); fph[b] ^= 1;
                asm volatile("fence.proxy.async.shared::cta;" ::: "memory");
                uint32_t st = base + b * STAGE_BYTES;
                uint64_t ad = DESC_SW64 | ((uint64_t)(st >> 4) & 0x3FFF);
                uint64_t bd = DESC_SW64 | ((uint64_t)((st + 8192) >> 4) & 0x3FFF);
                #pragma unroll
                for (int ks = 0; ks < 2; ks++)   // 2 x K=16 bf16 MMAs per stage
                    mma_bf16_ss(tmem, ad + 2 * ks, bd + 2 * ks,
                                IDESC_BF16, (s | ks) != 0);
                asm volatile("tcgen05.commit.cta_group::1.mbarrier::arrive::one.shared::cluster.b64 [%0];"
                             :: "r"(doneb[b]) : "memory");
            }
        }
    } else {
        int dph[3] = {0, 0, 0};
        for (int s = 3; s < S; s++) {
            int b = s % 3;
            mbar_wait(doneb[b], dph[b]); dph[b] ^= 1;
            load_stage(s);
        }
        int bl = (S - 1) % 3;
        mbar_wait(doneb[bl], dph[bl]);
    }
    __syncthreads();

    asm volatile("tcgen05.fence::after_thread_sync;" ::: "memory");
    if (wid < 8) {
        int row = m0 + ((wid & 3) << 5) + lane;
        int rrow_i = (EPI == 5) ? perm_row(row) : row;   // residual source row
        int srow_i = (EPI == 6) ? perm_row(row) : row;   // store destination row
        int colbase = (wid >> 2) << 6;
        uint32_t toff = tmem + ((uint32_t)(wid & 3) << 21);
        #pragma unroll
        for (int g = 0; g < 4; g++) {
            int col = colbase + g * 16;
            uint32_t r[16];
            LDTM_X16(r, toff + col);
            asm volatile("tcgen05.wait::ld.sync.aligned;" ::: "memory");
            float* crow = C + (size_t)srow_i * N + n0 + col;
            __nv_bfloat16* crow16 = (__nv_bfloat16*)C + (size_t)srow_i * N + n0 + col;
            const float4* rrow = (EPI >= 3)
                ? (const float4*)(res + (size_t)rrow_i * N + n0 + col) : nullptr;
            const float4* b4 = (EPI == 2 || EPI == 3 || EPI == 6)
                ? (const float4*)(bias + n0 + col) : nullptr;
            #pragma unroll
            for (int j = 0; j < 16; j += 4) {
                float4 v;
                v.x = __uint_as_float(r[j + 0]);
                v.y = __uint_as_float(r[j + 1]);
                v.z = __uint_as_float(r[j + 2]);
                v.w = __uint_as_float(r[j + 3]);
                if (EPI == 2 || EPI == 3 || EPI == 6) {
                    float4 bb = b4[j >> 2];
                    v.x += bb.x; v.y += bb.y; v.z += bb.z; v.w += bb.w;
                }
                if (EPI == 2) {
                    v.x = gelu_tanh(v.x); v.y = gelu_tanh(v.y);
                    v.z = gelu_tanh(v.z); v.w = gelu_tanh(v.w);
                    __nv_bfloat162 p0 = __floats2bfloat162_rn(v.x, v.y);
                    __nv_bfloat162 p1 = __floats2bfloat162_rn(v.z, v.w);
                    *(__nv_bfloat162*)(crow16 + j)     = p0;
                    *(__nv_bfloat162*)(crow16 + j + 2) = p1;
                } else {
                    if (EPI >= 3) {
                        float4 rr = rrow[j >> 2];
                        v.x += rr.x; v.y += rr.y; v.z += rr.z; v.w += rr.w;
                    }
                    *(float4*)(crow + j) = v;
                }
            }
        }
    }
    __syncthreads();
    if (wid == 0)
        asm volatile("tcgen05.dealloc.cta_group::1.sync.aligned.b32 %0, %1;"
                     :: "r"(tmem), "r"(128));
#else
    // ---------- SIMT fallback (plain sm_103 target; never selected at runtime) ----------
    (void)smem;
    int tid = threadIdx.x;
    int m0 = blockIdx.y << 7;
    int n0 = blockIdx.x << 7;
    for (int e = tid; e < 128 * 128; e += 288) {
        int i = e >> 7, j = e & 127;
        int row = m0 + i, coln = n0 + j;
        int rrow_i = (EPI == 5) ? perm_row(row) : row;
        int srow_i = (EPI == 6) ? perm_row(row) : row;
        float acc = 0.0f;
        for (int k = 0; k < K; k++)
            acc += __bfloat162float(A[(size_t)row * K + k]) *
                   __bfloat162float(B[(size_t)coln * K + k]);
        float v = acc;
        if (EPI == 2 || EPI == 3 || EPI == 6) v += bias[coln];
        if (EPI == 2) {
            ((__nv_bfloat16*)C)[(size_t)srow_i * N + coln] = __float2bfloat16(gelu_tanh(v));
        } else {
            if (EPI >= 3) v += res[(size_t)rrow_i * N + coln];
            C[(size_t)srow_i * N + coln] = v;
        }
    }
#endif
}

// ---------------- windowed attention: fp32 qkv in, bf16 o out ----------------
__global__ __launch_bounds__(224) void attn_kernel(const float* __restrict__ qkv,
                                                   const float* __restrict__ rpb,
                                                   __nv_bfloat16* __restrict__ o) {
    __shared__ float sQ[NT * 32];
    __shared__ float sK[NT * 36];
    __shared__ float sV[NT * 32];
    __shared__ float sS[NT * 52];
    __shared__ float sB[169];

    int w = blockIdx.x / HEADS, hh = blockIdx.x % HEADS;
    int tid = threadIdx.x, warp = tid >> 5, lane = tid & 31;
    const float* basep = qkv + (size_t)(w * NT) * (3 * CC) + hh * HD;

    for (int i = tid; i < NT * 8; i += 224) {
        int t = i >> 3, d4 = i & 7;
        const float4* p = (const float4*)(basep + (size_t)t * (3 * CC));
        *(float4*)&sQ[t * 32 + d4 * 4] = p[d4];
        *(float4*)&sK[t * 36 + d4 * 4] = p[96 + d4];
        *(float4*)&sV[t * 32 + d4 * 4] = p[192 + d4];
    }
    for (int i = tid; i < 169; i += 224) sB[i] = rpb[i * HEADS + hh];
    __syncthreads();

    const float scale = 0.17677669529663687f;
    int q0 = warp * 7;
    int k1 = lane, k2 = lane + 32;

    {
        float a0[7], a1[7];
        #pragma unroll
        for (int i = 0; i < 7; i++) { a0[i] = 0.0f; a1[i] = 0.0f; }
        #pragma unroll
        for (int d4 = 0; d4 < 8; d4++) {
            float4 kv1 = *(const float4*)&sK[k1 * 36 + d4 * 4];
            float4 kv2 = (k2 < NT) ? *(const float4*)&sK[k2 * 36 + d4 * 4]
                                   : make_float4(0.f, 0.f, 0.f, 0.f);
            #pragma unroll
            for (int i = 0; i < 7; i++) {
                float4 qv = *(const float4*)&sQ[(q0 + i) * 32 + d4 * 4];
                a0[i] += qv.x * kv1.x + qv.y * kv1.y + qv.z * kv1.z + qv.w * kv1.w;
                a1[i] += qv.x * kv2.x + qv.y * kv2.y + qv.z * kv2.z + qv.w * kv2.w;
            }
        }
        int k1y = k1 / WS, k1x = k1 - k1y * WS;
        int k2y = k2 / WS, k2x = k2 - k2y * WS;
        #pragma unroll
        for (int i = 0; i < 7; i++) {
            int q = q0 + i;
            int qy = q / WS, qx = q - qy * WS;
            sS[q * 52 + k1] = a0[i] * scale + sB[(qy - k1y + 6) * 13 + (qx - k1x + 6)];
            if (k2 < NT)
                sS[q * 52 + k2] = a1[i] * scale + sB[(qy - k2y + 6) * 13 + (qx - k2x + 6)];
        }
    }
    __syncthreads();

    #pragma unroll
    for (int i = 0; i < 7; i++) {
        int row = q0 + i;
        float v0 = sS[row * 52 + lane];
        float v1 = (lane < 17) ? sS[row * 52 + 32 + lane] : -INFINITY;
        float m = fmaxf(v0, v1);
        #pragma unroll
        for (int ofs = 16; ofs; ofs >>= 1) m = fmaxf(m, __shfl_xor_sync(0xffffffffu, m, ofs));
        float e0 = __expf(v0 - m);
        float e1 = (lane < 17) ? __expf(v1 - m) : 0.0f;
        float sum = e0 + e1;
        #pragma unroll
        for (int ofs = 16; ofs; ofs >>= 1) sum += __shfl_xor_sync(0xffffffffu, sum, ofs);
        float inv = 1.0f / sum;
        sS[row * 52 + lane] = e0 * inv;
        if (lane < 17) sS[row * 52 + 32 + lane] = e1 * inv;
    }
    __syncthreads();

    {
        float outv[7];
        #pragma unroll
        for (int i = 0; i < 7; i++) outv[i] = 0.0f;
        #pragma unroll
        for (int k4 = 0; k4 < 48; k4 += 4) {
            float vk0 = sV[(k4 + 0) * 32 + lane];
            float vk1 = sV[(k4 + 1) * 32 + lane];
            float vk2 = sV[(k4 + 2) * 32 + lane];
            float vk3 = sV[(k4 + 3) * 32 + lane];
            #pragma unroll
            for (int i = 0; i < 7; i++) {
                float4 sv = *(const float4*)&sS[(q0 + i) * 52 + k4];
                outv[i] += sv.x * vk0 + sv.y * vk1 + sv.z * vk2 + sv.w * vk3;
            }
        }
        float vkl = sV[48 * 32 + lane];
        #pragma unroll
        for (int i = 0; i < 7; i++) outv[i] += sS[(q0 + i) * 52 + 48] * vkl;
        #pragma unroll
        for (int i = 0; i < 7; i++)
            o[(size_t)(w * NT + q0 + i) * CC + hh * HD + lane] = __float2bfloat16(outv[i]);
    }
}

// ---------------- launch ----------------
extern "C" void kernel_launch(void* const* d_in, const int* in_sizes, int n_in,
                              void* d_out, int out_size) {
    const float* x      = (const float*)d_in[0];
    const float* ln1_s  = (const float*)d_in[1];
    const float* ln1_b  = (const float*)d_in[2];
    const float* qkv_w  = (const float*)d_in[3];
    const float* rpb    = (const float*)d_in[4];
    const float* proj_w = (const float*)d_in[5];
    const float* ln2_s  = (const float*)d_in[6];
    const float* ln2_b  = (const float*)d_in[7];
    const float* mlp_w1 = (const float*)d_in[8];
    const float* mlp_b1 = (const float*)d_in[9];
    const float* mlp_w2 = (const float*)d_in[10];
    const float* mlp_b2 = (const float*)d_in[11];
    float* out = (float*)d_out;

    float *xw, *qkv;
    __nv_bfloat16 *h, *o, *hidden, *wT;
    cudaGetSymbolAddress((void**)&xw, g_xw);
    cudaGetSymbolAddress((void**)&h, g_h);
    cudaGetSymbolAddress((void**)&qkv, g_qkv);
    cudaGetSymbolAddress((void**)&o, g_o);
    cudaGetSymbolAddress((void**)&hidden, g_hidden);
    cudaGetSymbolAddress((void**)&wT, g_wT);

    const int SMEM_SZ = 1024 + NSTAGE * STAGE_BYTES + 64;
    cudaFuncSetAttribute(tc_gemm<0>, cudaFuncAttributeMaxDynamicSharedMemorySize, SMEM_SZ);
    cudaFuncSetAttribute(tc_gemm<2>, cudaFuncAttributeMaxDynamicSharedMemorySize, SMEM_SZ);
    cudaFuncSetAttribute(tc_gemm<3>, cudaFuncAttributeMaxDynamicSharedMemorySize, SMEM_SZ);
    cudaFuncSetAttribute(tc_gemm<4>, cudaFuncAttributeMaxDynamicSharedMemorySize, SMEM_SZ);
    cudaFuncSetAttribute(tc_gemm<5>, cudaFuncAttributeMaxDynamicSharedMemorySize, SMEM_SZ);
    cudaFuncSetAttribute(tc_gemm<6>, cudaFuncAttributeMaxDynamicSharedMemorySize, SMEM_SZ);

    transpose_all<<<dim3(1728, 2), dim3(32, 8)>>>(qkv_w, proj_w, mlp_w1, mlp_w2, wT);

    const int MT = MROWS / 128;  // 392
    for (int l = 0; l < 2; l++) {
        __nv_bfloat16* wl = wT + (size_t)l * WT_LAYER;
        if (l == 0)
            ln_kernel<1><<<MROWS / 8, 256>>>(x, ln1_s, ln1_b, h);
        else
            ln_kernel<0><<<MROWS / 8, 256>>>(xw, ln1_s + CC, ln1_b + CC, h);
        tc_gemm<0><<<dim3(9, MT), 288, SMEM_SZ>>>(h, wl + OFF_QKV, nullptr, nullptr, qkv, 384, 1152);
        attn_kernel<<<NWIN * HEADS, 224>>>(qkv, rpb + (size_t)l * 169 * HEADS, o);
        if (l == 0)
            tc_gemm<5><<<dim3(3, MT), 288, SMEM_SZ>>>(o, wl + OFF_PROJ, nullptr, x, xw, 384, 384);
        else
            tc_gemm<4><<<dim3(3, MT), 288, SMEM_SZ>>>(o, wl + OFF_PROJ, nullptr, xw, xw, 384, 384);
        ln_kernel<0><<<MROWS / 8, 256>>>(xw, ln2_s + l * CC, ln2_b + l * CC, h);
        tc_gemm<2><<<dim3(12, MT), 288, SMEM_SZ>>>(h, wl + OFF_W1, mlp_b1 + (size_t)l * 1536,
                                                   nullptr, (float*)hidden, 384, 1536);
        if (l == 0)
            tc_gemm<3><<<dim3(3, MT), 288, SMEM_SZ>>>(hidden, wl + OFF_W2, mlp_b2,
                                                      xw, xw, 1536, 384);
        else
            tc_gemm<6><<<dim3(3, MT), 288, SMEM_SZ>>>(hidden, wl + OFF_W2, mlp_b2 + 384,
                                                      xw, out, 1536, 384);
    }
}